// round 15
// baseline (speedup 1.0000x reference)
#include <cuda_runtime.h>
#include <cuda_fp16.h>
#include <math.h>
#include <stdint.h>

// ---------------- problem constants ----------------
#define B_    32
#define L_    12
#define N_    512
#define D_    128
#define BN_   16384
#define LBN_  196608
#define FK_   256
#define T_    12
#define RES_ELEMS  25165824ULL
#define FORE_ELEMS 50331648ULL

// ---------------- device scratch ----------------
__device__ __half g_Xs    [(size_t)LBN_ * 128];
__device__ __half g_GI    [(size_t)LBN_ * 384];
__device__ __half g_GH    [(size_t)BN_  * 384];
__device__ __half g_rnn   [(size_t)LBN_ * 128];
__device__ __half g_rnnpe [(size_t)LBN_ * 128];
__device__ __half g_QKV   [(size_t)LBN_ * 384];
__device__ __half g_attn  [(size_t)LBN_ * 128];
__device__ __half g_Kc    [(size_t)23 * BN_ * 128];
__device__ __half g_Vc    [(size_t)23 * BN_ * 128];
__device__ __half g_aresU [(size_t)12 * BN_ * 128];   // slot 0 = attn last, 1..11 = decode outs
__device__ __half g_Qbuf  [(size_t)BN_ * 128];
__device__ __half g_GIdec [(size_t)BN_ * 384];
__device__ __half g_GHdec [(size_t)BN_ * 384];
__device__ __half g_g     [(size_t)BN_ * 128];
__device__ __half g_hlast [(size_t)BN_ * 128];
__device__ float  g_pe    [64 * 128];
__device__ float  g_Kpe   [24 * 128];
__device__ float  g_Vpe   [24 * 128];
// fp16 weights
__device__ __half g_wih_h  [49152];
__device__ __half g_whh_h  [49152];
__device__ __half g_inw_h  [49152];
__device__ __half g_Wf     [49152];
__device__ float  g_bf     [384];
__device__ __half g_Wbo    [16384];
__device__ float  g_bbo    [128];
__device__ __half g_Wfo    [32768];
__device__ float  g_ffo    [256];

// ---------------- helpers ----------------
__device__ __forceinline__ void mma16(float c[4], const unsigned a[4],
                                      unsigned b0, unsigned b1) {
    asm volatile(
        "mma.sync.aligned.m16n8k16.row.col.f32.f16.f16.f32 "
        "{%0,%1,%2,%3}, {%4,%5,%6,%7}, {%8,%9}, {%0,%1,%2,%3};\n"
        : "+f"(c[0]), "+f"(c[1]), "+f"(c[2]), "+f"(c[3])
        : "r"(a[0]), "r"(a[1]), "r"(a[2]), "r"(a[3]), "r"(b0), "r"(b1));
}
__device__ __forceinline__ float sigmoid_f(float x) {
    return __fdividef(1.f, 1.f + __expf(-x));
}
__device__ __forceinline__ float tanh_f(float x) {
    float ex = __expf(2.f * x);
    return 1.f - __fdividef(2.f, ex + 1.f);
}

#define CP16(dst, src) asm volatile("cp.async.cg.shared.global [%0], [%1], 16;" :: "r"(dst), "l"(src))

// ---------------- fp16 tensor-core GEMM (m16n8k16), BK=32, 3-stage cp.async ----------------
// C = A[M,128] @ W[N,128]^T + bias. smem row stride 40 halves (conflict-free frags).
// MODE 0 plain fp16 out. 3 QKV + K/V scatter (N=384). 4 proj: Q + K/V scatter at pos (N=384).
// 6 backcast+LN fused fp32 (N=128). 7 forecast slice at timestep pos (M=BN, N=256).
#define GSTAGE_H 10240          // A (128x40=5120) + W (5120) halves per stage
#define GSMEM_BYTES (3 * GSTAGE_H * 2)

template <int MODE>
__global__ __launch_bounds__(256, 2) void gemm3(
    const __half* __restrict__ A, const __half* __restrict__ W,
    const float* __restrict__ bias, void* __restrict__ C,
    int M, int N, int pos,
    __half* __restrict__ Kc, __half* __restrict__ Vc,
    const float* __restrict__ Xg, const float* __restrict__ gammap,
    const float* __restrict__ betap)
{
    extern __shared__ __half smh[];

    const int tid = threadIdx.x, lane = tid & 31, warp = tid >> 5;
    const int wm = (warp >> 2) * 64;
    const int wn = (warp & 3) * 32;
    const int blockM = blockIdx.y * 128;
    const int blockN = blockIdx.x * 128;

    // loader mapping: 2 cp.async per matrix per stage per thread
    const int lrow = tid >> 2;          // 0..63
    const int koff = (tid & 3) * 8;     // 0,8,16,24
    const __half* Ag = A + (size_t)(blockM + lrow) * 128 + koff;
    const __half* Wg = W + (size_t)(blockN + lrow) * 128 + koff;
    uint32_t smb = (uint32_t)__cvta_generic_to_shared(smh);
    uint32_t a_s0 = smb + (uint32_t)(lrow * 40 + koff) * 2;
    uint32_t w_s0 = smb + (uint32_t)(5120 + lrow * 40 + koff) * 2;

    #define LOADSTAGE(S, KB) do { \
        uint32_t as_ = a_s0 + (S) * (GSTAGE_H * 2); \
        uint32_t ws_ = w_s0 + (S) * (GSTAGE_H * 2); \
        CP16(as_,                Ag + (KB)); \
        CP16(as_ + 64 * 40 * 2,  Ag + 64 * 128 + (KB)); \
        CP16(ws_,                Wg + (KB)); \
        CP16(ws_ + 64 * 40 * 2,  Wg + 64 * 128 + (KB)); \
    } while (0)

    float c[4][4][4];
    #pragma unroll
    for (int i = 0; i < 4; i++)
        #pragma unroll
        for (int j = 0; j < 4; j++)
            #pragma unroll
            for (int r = 0; r < 4; r++) c[i][j][r] = 0.f;

    LOADSTAGE(0, 0);
    asm volatile("cp.async.commit_group;");
    LOADSTAGE(1, 32);
    asm volatile("cp.async.commit_group;");

    const int kq = (lane & 3) * 2;
    #pragma unroll
    for (int it = 0; it < 4; ++it) {
        asm volatile("cp.async.wait_group 1;");
        __syncthreads();
        if (it + 2 < 4) LOADSTAGE((it + 2) % 3, (it + 2) * 32);
        asm volatile("cp.async.commit_group;");

        const __half* Ab = smh + (it % 3) * GSTAGE_H;
        const __half* Wb = Ab + 5120;
        #pragma unroll
        for (int ks = 0; ks < 32; ks += 16) {
            unsigned af[4][4];
            #pragma unroll
            for (int mt = 0; mt < 4; mt++) {
                int row = wm + mt * 16 + (lane >> 2);
                af[mt][0] = *(const unsigned*)(Ab + row * 40 + kq + ks);
                af[mt][1] = *(const unsigned*)(Ab + (row + 8) * 40 + kq + ks);
                af[mt][2] = *(const unsigned*)(Ab + row * 40 + kq + ks + 8);
                af[mt][3] = *(const unsigned*)(Ab + (row + 8) * 40 + kq + ks + 8);
            }
            #pragma unroll
            for (int nt = 0; nt < 4; nt++) {
                int col = wn + nt * 8 + (lane >> 2);
                unsigned b0 = *(const unsigned*)(Wb + col * 40 + kq + ks);
                unsigned b1 = *(const unsigned*)(Wb + col * 40 + kq + ks + 8);
                #pragma unroll
                for (int mt = 0; mt < 4; mt++)
                    mma16(c[mt][nt], af[mt], b0, b1);
            }
        }
    }
    #undef LOADSTAGE

    // ================= epilogues =================
    if (MODE == 6) {
        asm volatile("cp.async.wait_group 0;");
        __syncthreads();
        float* sf = reinterpret_cast<float*>(smh);
        float* ssum = sf;
        float* ssq  = sf + 512;
        float ps[8], pq[8];
        #pragma unroll
        for (int p = 0; p < 8; p++) { ps[p] = 0.f; pq[p] = 0.f; }
        size_t xr[8];
        #pragma unroll
        for (int mt = 0; mt < 4; mt++) {
            int gr0 = blockM + wm + mt * 16 + (lane >> 2);
            int gr1 = gr0 + 8;
            int l0 = gr0 >> 14, r0 = gr0 & 16383;
            xr[mt * 2]     = (((size_t)((r0 >> 9) * 12 + l0) * 512 + (r0 & 511)) << 7);
            int l1 = gr1 >> 14, r1 = gr1 & 16383;
            xr[mt * 2 + 1] = (((size_t)((r1 >> 9) * 12 + l1) * 512 + (r1 & 511)) << 7);
            #pragma unroll
            for (int nt = 0; nt < 4; nt++) {
                int gc = wn + nt * 8 + 2 * (lane & 3);
                float bv0 = bias[gc], bv1 = bias[gc + 1];
                float u00 = Xg[xr[mt*2]   + gc]     - fmaxf(c[mt][nt][0] + bv0, 0.f);
                float u01 = Xg[xr[mt*2]   + gc + 1] - fmaxf(c[mt][nt][1] + bv1, 0.f);
                float u10 = Xg[xr[mt*2+1] + gc]     - fmaxf(c[mt][nt][2] + bv0, 0.f);
                float u11 = Xg[xr[mt*2+1] + gc + 1] - fmaxf(c[mt][nt][3] + bv1, 0.f);
                c[mt][nt][0] = u00; c[mt][nt][1] = u01;
                c[mt][nt][2] = u10; c[mt][nt][3] = u11;
                ps[mt*2]   += u00 + u01;  pq[mt*2]   += u00*u00 + u01*u01;
                ps[mt*2+1] += u10 + u11;  pq[mt*2+1] += u10*u10 + u11*u11;
            }
        }
        #pragma unroll
        for (int o = 1; o < 4; o <<= 1) {
            #pragma unroll
            for (int p = 0; p < 8; p++) {
                ps[p] += __shfl_xor_sync(0xffffffffu, ps[p], o);
                pq[p] += __shfl_xor_sync(0xffffffffu, pq[p], o);
            }
        }
        int wnIdx = warp & 3;
        if ((lane & 3) == 0) {
            #pragma unroll
            for (int mt = 0; mt < 4; mt++) {
                int lr = wm + mt * 16 + (lane >> 2);
                ssum[wnIdx * 128 + lr]     = ps[mt*2];
                ssq [wnIdx * 128 + lr]     = pq[mt*2];
                ssum[wnIdx * 128 + lr + 8] = ps[mt*2+1];
                ssq [wnIdx * 128 + lr + 8] = pq[mt*2+1];
            }
        }
        __syncthreads();
        float* Cf = (float*)C;
        #pragma unroll
        for (int mt = 0; mt < 4; mt++) {
            int lr0 = wm + mt * 16 + (lane >> 2);
            int lr1 = lr0 + 8;
            float s0 = ssum[lr0] + ssum[128+lr0] + ssum[256+lr0] + ssum[384+lr0];
            float q0 = ssq[lr0]  + ssq[128+lr0]  + ssq[256+lr0]  + ssq[384+lr0];
            float s1 = ssum[lr1] + ssum[128+lr1] + ssum[256+lr1] + ssum[384+lr1];
            float q1 = ssq[lr1]  + ssq[128+lr1]  + ssq[256+lr1]  + ssq[384+lr1];
            float mu0 = s0 * (1.f/128.f);
            float iv0 = rsqrtf(q0 * (1.f/128.f) - mu0*mu0 + 1e-5f);
            float mu1 = s1 * (1.f/128.f);
            float iv1 = rsqrtf(q1 * (1.f/128.f) - mu1*mu1 + 1e-5f);
            #pragma unroll
            for (int nt = 0; nt < 4; nt++) {
                int gc = wn + nt * 8 + 2 * (lane & 3);
                float g0 = gammap[gc], g1 = gammap[gc+1];
                float b0 = betap[gc],  b1 = betap[gc+1];
                Cf[xr[mt*2]   + gc]     = (c[mt][nt][0] - mu0) * iv0 * g0 + b0;
                Cf[xr[mt*2]   + gc + 1] = (c[mt][nt][1] - mu0) * iv0 * g1 + b1;
                Cf[xr[mt*2+1] + gc]     = (c[mt][nt][2] - mu1) * iv1 * g0 + b0;
                Cf[xr[mt*2+1] + gc + 1] = (c[mt][nt][3] - mu1) * iv1 * g1 + b1;
            }
        }
        return;
    }

    #pragma unroll
    for (int mt = 0; mt < 4; mt++) {
        #pragma unroll
        for (int nt = 0; nt < 4; nt++) {
            int gr = blockM + wm + mt * 16 + (lane >> 2);
            int gc = blockN + wn + nt * 8 + 2 * (lane & 3);
            float bv0 = bias[gc], bv1 = bias[gc + 1];
            float v00 = c[mt][nt][0] + bv0, v01 = c[mt][nt][1] + bv1;
            float v10 = c[mt][nt][2] + bv0, v11 = c[mt][nt][3] + bv1;
            int gr1 = gr + 8;
            __half2 h0 = __floats2half2_rn(v00, v01);
            __half2 h1 = __floats2half2_rn(v10, v11);
            if (MODE == 0) {
                __half* Ch = (__half*)C;
                *(__half2*)(Ch + (size_t)gr * N + gc)  = h0;
                *(__half2*)(Ch + (size_t)gr1 * N + gc) = h1;
            } else if (MODE == 7) {
                float* Cf = (float*)C;
                size_t or0 = (size_t)((gr  >> 9) * 12 + pos) * 512 + (gr  & 511);
                size_t or1 = (size_t)((gr1 >> 9) * 12 + pos) * 512 + (gr1 & 511);
                float* p0 = Cf + or0 * 256 + gc;
                float* p1 = Cf + or1 * 256 + gc;
                p0[0] = v00; p0[1] = v01; p1[0] = v10; p1[1] = v11;
            } else if (MODE == 3) {
                __half* Ch = (__half*)C;
                *(__half2*)(Ch + (size_t)gr * N + gc)  = h0;
                *(__half2*)(Ch + (size_t)gr1 * N + gc) = h1;
                if (gc >= 128 && gc < 256) {
                    *(__half2*)(Kc + (size_t)gr * 128 + gc - 128)  = h0;
                    *(__half2*)(Kc + (size_t)gr1 * 128 + gc - 128) = h1;
                } else if (gc >= 256) {
                    *(__half2*)(Vc + (size_t)gr * 128 + gc - 256)  = h0;
                    *(__half2*)(Vc + (size_t)gr1 * 128 + gc - 256) = h1;
                }
            } else { // MODE 4
                __half* Ch = (__half*)C;
                if (gc < 128) {
                    *(__half2*)(Ch + (size_t)gr * 128 + gc)  = h0;
                    *(__half2*)(Ch + (size_t)gr1 * 128 + gc) = h1;
                } else if (gc < 256) {
                    *(__half2*)(Kc + ((size_t)pos * BN_ + gr) * 128 + gc - 128)  = h0;
                    *(__half2*)(Kc + ((size_t)pos * BN_ + gr1) * 128 + gc - 128) = h1;
                } else {
                    *(__half2*)(Vc + ((size_t)pos * BN_ + gr) * 128 + gc - 256)  = h0;
                    *(__half2*)(Vc + ((size_t)pos * BN_ + gr1) * 128 + gc - 256) = h1;
                }
            }
        }
    }
}

// ---------------- prep kernels ----------------
__global__ void pe_init_kernel(float* pe) {
    int idx = blockIdx.x * blockDim.x + threadIdx.x;
    if (idx >= 64 * 128) return;
    int pos = idx >> 7, d = idx & 127;
    int j = d >> 1;
    float div = expf((float)(2 * j) * (-logf(10000.f) / 128.f));
    float ang = (float)pos * div;
    pe[idx] = (d & 1) ? cosf(ang) : sinf(ang);
}

__global__ void halfw_a_kernel(const float* __restrict__ w_ih, const float* __restrict__ w_hh,
                               const float* __restrict__ in_w,
                               __half* wih, __half* whh, __half* inw) {
    int i = blockIdx.x * blockDim.x + threadIdx.x;
    if (i < 49152)       wih[i]         = __float2half(w_ih[i]);
    else if (i < 98304)  whh[i - 49152] = __float2half(w_hh[i - 49152]);
    else if (i < 147456) inw[i - 98304] = __float2half(in_w[i - 98304]);
}

__global__ void xconv_kernel(const float* __restrict__ X, __half* __restrict__ Xs) {
    int idx = blockIdx.x * blockDim.x + threadIdx.x;
    if (idx >= LBN_ * 32) return;
    int d4 = (idx & 31) * 4;
    int row = idx >> 5;
    int l = row >> 14, rem = row & 16383, b = rem >> 9, n = rem & 511;
    float4 v = *(const float4*)(X + (((size_t)(b * 12 + l) * 512 + n) << 7) + d4);
    *(__half2*)(Xs + (size_t)row * 128 + d4)     = __floats2half2_rn(v.x, v.y);
    *(__half2*)(Xs + (size_t)row * 128 + d4 + 2) = __floats2half2_rn(v.z, v.w);
}

__global__ void prefuse_kernel(const float* __restrict__ W1, const float* __restrict__ W2,
                               const float* __restrict__ b2, const float* __restrict__ b1,
                               __half* __restrict__ Wout, float* __restrict__ bout, int R) {
    int idx = blockIdx.x * blockDim.x + threadIdx.x;
    if (idx >= R * 128) return;
    int r = idx >> 7, k = idx & 127;
    float acc = 0.f;
    #pragma unroll 4
    for (int j = 0; j < 128; j++) acc += W1[r * 128 + j] * W2[j * 128 + k];
    Wout[idx] = __float2half(acc);
    if (k == 0) {
        float b = 0.f;
        for (int j = 0; j < 128; j++) b += W1[r * 128 + j] * b2[j];
        bout[r] = b + (b1 ? b1[r] : 0.f);
    }
}

__global__ void kvpe_kernel(const float* __restrict__ attn_in_w, const float* __restrict__ pe,
                            float* __restrict__ Kpe, float* __restrict__ Vpe) {
    int idx = blockIdx.x * blockDim.x + threadIdx.x;
    if (idx >= 24 * 256) return;
    int pos = idx >> 8, c = idx & 255;
    const float* wrow = attn_in_w + (size_t)(128 + c) * 128;
    const float* prow = pe + pos * 128;
    float acc = 0.f;
    #pragma unroll 4
    for (int d = 0; d < 128; d++) acc += wrow[d] * prow[d];
    if (c < 128) Kpe[pos * 128 + c] = acc;
    else         Vpe[pos * 128 + (c - 128)] = acc;
}

// ---------------- GRU gates (fp16 I/O, half2-vectorized) ----------------
__global__ void gru_gates_kernel(const __half* __restrict__ gi, const __half* __restrict__ gh,
                                 const __half* __restrict__ h, __half* __restrict__ hnew,
                                 __half* __restrict__ hnext, const float* __restrict__ pe_row,
                                 const float* __restrict__ bhh, int total2) {
    int idx = blockIdx.x * blockDim.x + threadIdx.x;
    if (idx >= total2) return;
    int row = idx >> 6, d2 = (idx & 63) * 2;
    size_t b3 = (size_t)row * 384;
    float2 ir  = __half22float2(*(const __half2*)(gi + b3 + d2));
    float2 iz  = __half22float2(*(const __half2*)(gi + b3 + 128 + d2));
    float2 in_ = __half22float2(*(const __half2*)(gi + b3 + 256 + d2));
    float2 hr, hz, hn;
    if (gh) {
        hr = __half22float2(*(const __half2*)(gh + b3 + d2));
        hz = __half22float2(*(const __half2*)(gh + b3 + 128 + d2));
        hn = __half22float2(*(const __half2*)(gh + b3 + 256 + d2));
    } else {
        hr = make_float2(bhh[d2], bhh[d2 + 1]);
        hz = make_float2(bhh[128 + d2], bhh[128 + d2 + 1]);
        hn = make_float2(bhh[256 + d2], bhh[256 + d2 + 1]);
    }
    float2 hv = h ? __half22float2(*(const __half2*)(h + (size_t)row * 128 + d2))
                  : make_float2(0.f, 0.f);
    float r0 = sigmoid_f(ir.x + hr.x), r1 = sigmoid_f(ir.y + hr.y);
    float z0 = sigmoid_f(iz.x + hz.x), z1 = sigmoid_f(iz.y + hz.y);
    float n0 = tanh_f(in_.x + r0 * hn.x), n1 = tanh_f(in_.y + r1 * hn.y);
    float o0 = (1.f - z0) * n0 + z0 * hv.x;
    float o1 = (1.f - z1) * n1 + z1 * hv.y;
    *(__half2*)(hnew + (size_t)row * 128 + d2) = __floats2half2_rn(o0, o1);
    if (hnext)
        *(__half2*)(hnext + (size_t)row * 128 + d2) =
            __floats2half2_rn(o0 + pe_row[d2], o1 + pe_row[d2 + 1]);
}

// ---------------- encoder self-attention ----------------
__global__ void enc_attn_kernel(const __half* __restrict__ QKV, __half* __restrict__ O,
                                __half* __restrict__ ares0) {
    int bn = blockIdx.x;
    int w = threadIdx.x >> 5, lane = threadIdx.x & 31;
    __shared__ float q[4][12][32];
    __shared__ float k[4][12][33];
    __shared__ float v[4][12][33];
    __shared__ float s[4][12][13];

    for (int e = lane; e < 12 * 16; e += 32) {
        int l = e >> 4, d2 = (e & 15) * 2;
        size_t base = ((size_t)l * BN_ + bn) * 384 + w * 32 + d2;
        float2 qv = __half22float2(*(const __half2*)(QKV + base));
        float2 kv = __half22float2(*(const __half2*)(QKV + base + 128));
        float2 vv = __half22float2(*(const __half2*)(QKV + base + 256));
        q[w][l][d2] = qv.x; q[w][l][d2+1] = qv.y;
        k[w][l][d2] = kv.x; k[w][l][d2+1] = kv.y;
        v[w][l][d2] = vv.x; v[w][l][d2+1] = vv.y;
    }
    __syncwarp();
    const float scale = 0.17677669529663687f;
    if (lane < 12) {
        int j = lane;
        #pragma unroll
        for (int i = 0; i < 12; i++) {
            float acc = 0.f;
            #pragma unroll
            for (int d = 0; d < 32; d++) acc += q[w][i][d] * k[w][j][d];
            s[w][i][j] = acc * scale;
        }
    }
    __syncwarp();
    if (lane < 12) {
        int i = lane;
        float mx = -1e30f;
        #pragma unroll
        for (int j = 0; j < 12; j++) mx = fmaxf(mx, s[w][i][j]);
        float sum = 0.f;
        #pragma unroll
        for (int j = 0; j < 12; j++) { float e = __expf(s[w][i][j] - mx); s[w][i][j] = e; sum += e; }
        float inv = __fdividef(1.f, sum);
        #pragma unroll
        for (int j = 0; j < 12; j++) s[w][i][j] *= inv;
    }
    __syncwarp();
    {
        int d = lane;
        #pragma unroll
        for (int i = 0; i < 12; i++) {
            float acc = 0.f;
            #pragma unroll
            for (int j = 0; j < 12; j++) acc += s[w][i][j] * v[w][j][d];
            __half hv = __float2half(acc);
            O[((size_t)i * BN_ + bn) * 128 + w * 32 + d] = hv;
            if (i == 11) ares0[(size_t)bn * 128 + w * 32 + d] = hv;
        }
    }
}

// ---------------- decode attention (fp16 KV/Q, PE-drift multipliers) ----------------
__global__ void dec_attn_kernel(const __half* __restrict__ Qbuf,
                                const __half* __restrict__ Kc, const __half* __restrict__ Vc,
                                const float* __restrict__ Kpe, const float* __restrict__ Vpe,
                                __half* __restrict__ O, int t) {
    int len = 12 + t;
    int bn = blockIdx.x;
    int w = threadIdx.x >> 5, lane = threadIdx.x & 31;
    __shared__ float qs[4][32];
    __shared__ float Kb[4][23][33];
    __shared__ float Vb[4][23][33];
    __shared__ float aw[4][23];

    qs[w][lane] = __half2float(Qbuf[(size_t)bn * 128 + w * 32 + lane]);
    for (int e = lane; e < len * 16; e += 32) {
        int i = e >> 4, d2 = (e & 15) * 2;
        size_t src = ((size_t)i * BN_ + bn) * 128 + w * 32 + d2;
        float2 kv = __half22float2(*(const __half2*)(Kc + src));
        float2 vv = __half22float2(*(const __half2*)(Vc + src));
        Kb[w][i][d2] = kv.x; Kb[w][i][d2+1] = kv.y;
        Vb[w][i][d2] = vv.x; Vb[w][i][d2+1] = vv.y;
    }
    __syncwarp();

    float sc = -1e30f;
    int i = lane;
    if (i < len) {
        float m = (i < 12) ? (float)(t - 1) : (float)(t - i + 12);
        float a = 0.f, ap = 0.f;
        #pragma unroll
        for (int d = 0; d < 32; d++) {
            float qd = qs[w][d];
            a  += Kb[w][i][d] * qd;
            ap += Kpe[i * 128 + w * 32 + d] * qd;
        }
        sc = (a + m * ap) * 0.17677669529663687f;
    }
    float mx = sc;
    #pragma unroll
    for (int o = 16; o > 0; o >>= 1) mx = fmaxf(mx, __shfl_xor_sync(0xffffffffu, mx, o));
    float e = (i < len) ? __expf(sc - mx) : 0.f;
    float sum = e;
    #pragma unroll
    for (int o = 16; o > 0; o >>= 1) sum += __shfl_xor_sync(0xffffffffu, sum, o);
    float a = __fdividef(e, sum);
    if (i < len) aw[w][i] = a;
    __syncwarp();

    int d = lane;
    float acc = 0.f;
    for (int j = 0; j < len; j++) {
        float mj = (j < 12) ? (float)(t - 1) : (float)(t - j + 12);
        acc += aw[w][j] * (Vb[w][j][d] + mj * Vpe[j * 128 + w * 32 + d]);
    }
    O[(size_t)bn * 128 + w * 32 + d] = __float2half(acc);
}

// ---------------- host ----------------
static inline float* symaddr(const void* sym) {
    void* p = nullptr;
    cudaGetSymbolAddress(&p, sym);
    return (float*)p;
}
static inline __half* symaddr_h(const void* sym) {
    void* p = nullptr;
    cudaGetSymbolAddress(&p, sym);
    return (__half*)p;
}

template <int MODE>
static inline void launch_gemm(cudaStream_t st,
                               const __half* A, const __half* W, const float* b, void* C,
                               int M, int N, int pos = 0,
                               __half* Kc = nullptr, __half* Vc = nullptr,
                               const float* Xg = nullptr,
                               const float* gam = nullptr, const float* bet = nullptr) {
    gemm3<MODE><<<dim3(N / 128, M / 128, 1), 256, GSMEM_BYTES, st>>>(
        A, W, b, C, M, N, pos, Kc, Vc, Xg, gam, bet);
}

extern "C" void kernel_launch(void* const* d_in, const int* in_sizes, int n_in,
                              void* d_out, int out_size) {
    const float* X          = (const float*)d_in[0];
    const float* gru_w_ih   = (const float*)d_in[1];
    const float* gru_w_hh   = (const float*)d_in[2];
    const float* gru_b_ih   = (const float*)d_in[3];
    const float* gru_b_hh   = (const float*)d_in[4];
    const float* attn_in_w  = (const float*)d_in[5];
    const float* attn_in_b  = (const float*)d_in[6];
    const float* attn_out_w = (const float*)d_in[7];
    const float* attn_out_b = (const float*)d_in[8];
    const float* backcast_w = (const float*)d_in[9];
    const float* backcast_b = (const float*)d_in[10];
    const float* forecast_w = (const float*)d_in[11];
    const float* forecast_b = (const float*)d_in[12];
    const float* ln_gamma   = (const float*)d_in[13];
    const float* ln_beta    = (const float*)d_in[14];

    float* out  = (float*)d_out;
    float* res  = out;
    float* fore = out + RES_ELEMS;

    __half* Xs     = symaddr_h(g_Xs);
    __half* GI     = symaddr_h(g_GI);
    __half* GH     = symaddr_h(g_GH);
    __half* rnn    = symaddr_h(g_rnn);
    __half* rnnpe  = symaddr_h(g_rnnpe);
    __half* QKV    = symaddr_h(g_QKV);
    __half* attn   = symaddr_h(g_attn);
    __half* Kc     = symaddr_h(g_Kc);
    __half* Vc     = symaddr_h(g_Vc);
    __half* aresU  = symaddr_h(g_aresU);
    __half* Qbuf   = symaddr_h(g_Qbuf);
    __half* GIdec  = symaddr_h(g_GIdec);
    __half* GHdec  = symaddr_h(g_GHdec);
    __half* gbuf   = symaddr_h(g_g);
    __half* hlast  = symaddr_h(g_hlast);
    float*  pe     = symaddr(g_pe);
    float*  Kpe    = symaddr(g_Kpe);
    float*  Vpe    = symaddr(g_Vpe);
    __half* wih_h  = symaddr_h(g_wih_h);
    __half* whh_h  = symaddr_h(g_whh_h);
    __half* inw_h  = symaddr_h(g_inw_h);
    __half* Wf     = symaddr_h(g_Wf);
    float*  bf     = symaddr(g_bf);
    __half* Wbo    = symaddr_h(g_Wbo);
    float*  bbo    = symaddr(g_bbo);
    __half* Wfo    = symaddr_h(g_Wfo);
    float*  ffo    = symaddr(g_ffo);

    static bool inited = false;
    static cudaStream_t s2 = 0, s3 = 0;
    static cudaEvent_t evF = 0, evB1 = 0, evEnc = 0, evM1 = 0, evW = 0, evS3 = 0;
    static cudaEvent_t evGH[13], evGate[13], evA[12];
    if (!inited) {
        cudaFuncSetAttribute(gemm3<0>, cudaFuncAttributeMaxDynamicSharedMemorySize, GSMEM_BYTES);
        cudaFuncSetAttribute(gemm3<3>, cudaFuncAttributeMaxDynamicSharedMemorySize, GSMEM_BYTES);
        cudaFuncSetAttribute(gemm3<4>, cudaFuncAttributeMaxDynamicSharedMemorySize, GSMEM_BYTES);
        cudaFuncSetAttribute(gemm3<6>, cudaFuncAttributeMaxDynamicSharedMemorySize, GSMEM_BYTES);
        cudaFuncSetAttribute(gemm3<7>, cudaFuncAttributeMaxDynamicSharedMemorySize, GSMEM_BYTES);
        cudaStreamCreateWithFlags(&s2, cudaStreamNonBlocking);
        cudaStreamCreateWithFlags(&s3, cudaStreamNonBlocking);
        cudaEventCreateWithFlags(&evF,   cudaEventDisableTiming);
        cudaEventCreateWithFlags(&evB1,  cudaEventDisableTiming);
        cudaEventCreateWithFlags(&evEnc, cudaEventDisableTiming);
        cudaEventCreateWithFlags(&evM1,  cudaEventDisableTiming);
        cudaEventCreateWithFlags(&evW,   cudaEventDisableTiming);
        cudaEventCreateWithFlags(&evS3,  cudaEventDisableTiming);
        for (int i = 0; i < 13; i++) {
            cudaEventCreateWithFlags(&evGH[i],   cudaEventDisableTiming);
            cudaEventCreateWithFlags(&evGate[i], cudaEventDisableTiming);
        }
        for (int i = 0; i < 12; i++)
            cudaEventCreateWithFlags(&evA[i], cudaEventDisableTiming);
        inited = true;
    }

    const int TPB = 256;
    const cudaStream_t s0 = 0;

    // ---- s0 prep (evF recorded first so side streams can fork legally) ----
    pe_init_kernel<<<(64 * 128 + TPB - 1) / TPB, TPB, 0, s0>>>(pe);
    cudaEventRecord(evF, s0);
    halfw_a_kernel<<<(147456 + TPB - 1) / TPB, TPB, 0, s0>>>(gru_w_ih, gru_w_hh, attn_in_w,
                                                             wih_h, whh_h, inw_h);
    xconv_kernel<<<LBN_ * 32 / TPB, TPB, 0, s0>>>(X, Xs);

    // ---- s3: fork off evF, weight prefusions ----
    cudaStreamWaitEvent(s3, evF, 0);
    prefuse_kernel<<<(49152 + TPB - 1) / TPB, TPB, 0, s3>>>(gru_w_ih, attn_out_w, attn_out_b,
                                                            gru_b_ih, Wf, bf, 384);
    prefuse_kernel<<<(16384 + TPB - 1) / TPB, TPB, 0, s3>>>(backcast_w, attn_out_w, attn_out_b,
                                                            backcast_b, Wbo, bbo, 128);
    prefuse_kernel<<<(32768 + TPB - 1) / TPB, TPB, 0, s3>>>(forecast_w, attn_out_w, attn_out_b,
                                                            forecast_b, Wfo, ffo, 256);
    cudaEventRecord(evW, s3);

    // ---- s2: fork off evF, kvpe ----
    cudaStreamWaitEvent(s2, evF, 0);
    kvpe_kernel<<<(24 * 256 + TPB - 1) / TPB, TPB, 0, s2>>>(attn_in_w, pe, Kpe, Vpe);
    cudaEventRecord(evB1, s2);

    // ---- GI for all encoder steps ----
    launch_gemm<0>(s0, Xs, wih_h, gru_b_ih, GI, LBN_, 384);

    // ---- GRU encode ----
    gru_gates_kernel<<<BN_ * 64 / TPB, TPB, 0, s0>>>(GI, nullptr, nullptr,
                                                     rnn, rnnpe, pe, gru_b_hh, BN_ * 64);
    for (int l = 1; l < 12; l++) {
        launch_gemm<0>(s0, rnn + (size_t)(l - 1) * BN_ * 128, whh_h, gru_b_hh, GH, BN_, 384);
        gru_gates_kernel<<<BN_ * 64 / TPB, TPB, 0, s0>>>(GI + (size_t)l * BN_ * 384, GH,
                                                         rnn + (size_t)(l - 1) * BN_ * 128,
                                                         rnn + (size_t)l * BN_ * 128,
                                                         rnnpe + (size_t)l * BN_ * 128,
                                                         pe + l * 128, nullptr, BN_ * 64);
    }
    cudaEventRecord(evEnc, s0);

    // ---- s2: GH_1 (needs rnn[11] only) ----
    cudaStreamWaitEvent(s2, evEnc, 0);
    launch_gemm<0>(s2, rnn + (size_t)11 * BN_ * 128, whh_h, gru_b_hh, GHdec, BN_, 384);
    cudaEventRecord(evGH[1], s2);

    // ---- encoder MHA ----
    launch_gemm<3>(s0, rnnpe, inw_h, attn_in_b, QKV, LBN_, 384, 0, Kc, Vc);
    enc_attn_kernel<<<BN_, 128, 0, s0>>>(QKV, attn, aresU);
    cudaEventRecord(evM1, s0);
    cudaEventRecord(evA[0], s0);

    // ---- s3: backcast + LN, then forecast slices as they become ready ----
    cudaStreamWaitEvent(s3, evM1, 0);
    launch_gemm<6>(s3, attn, Wbo, bbo, res, LBN_, 128, 0, nullptr, nullptr,
                   X, ln_gamma, ln_beta);
    cudaStreamWaitEvent(s3, evA[0], 0);
    launch_gemm<7>(s3, aresU, Wfo, ffo, fore, BN_, 256, 0);

    // ---- GI_1 (prefused Wf, A = aresU[0] = attn last) ----
    cudaStreamWaitEvent(s0, evW, 0);
    launch_gemm<0>(s0, aresU, Wf, bf, GIdec, BN_, 384);

    // ---- decode loop: gates -> proj -> attn -> GI_{t+1} on s0; GH on s2; fore slices on s3 ----
    cudaStreamWaitEvent(s0, evB1, 0);
    const __half* hl = rnn + (size_t)11 * BN_ * 128;
    for (int t = 1; t <= 11; t++) {
        cudaStreamWaitEvent(s0, evGH[t], 0);
        gru_gates_kernel<<<BN_ * 64 / TPB, TPB, 0, s0>>>(GIdec, GHdec, hl, gbuf,
                                                         hlast, pe + (11 + t) * 128,
                                                         nullptr, BN_ * 64);
        hl = hlast;
        if (t < 11) {
            cudaEventRecord(evGate[t], s0);
            cudaStreamWaitEvent(s2, evGate[t], 0);
            launch_gemm<0>(s2, hlast, whh_h, gru_b_hh, GHdec, BN_, 384);
            cudaEventRecord(evGH[t + 1], s2);
        }
        launch_gemm<4>(s0, gbuf, inw_h, attn_in_b, Qbuf, BN_, 384, 11 + t, Kc, Vc);
        dec_attn_kernel<<<BN_, 128, 0, s0>>>(Qbuf, Kc, Vc, Kpe, Vpe,
                                             aresU + (size_t)t * BN_ * 128, t);
        if (t < 11) {
            cudaEventRecord(evA[t], s0);
            cudaStreamWaitEvent(s3, evA[t], 0);
            launch_gemm<7>(s3, aresU + (size_t)t * BN_ * 128, Wfo, ffo, fore, BN_, 256, t);
            launch_gemm<0>(s0, aresU + (size_t)t * BN_ * 128, Wf, bf, GIdec, BN_, 384);
        }
    }
    cudaEventRecord(evS3, s3);

    // ---- tail: last forecast slice on s0, join s3 ----
    cudaStreamWaitEvent(s0, evS3, 0);
    launch_gemm<7>(s0, aresU + (size_t)11 * BN_ * 128, Wfo, ffo, fore, BN_, 256, 11);
}

// round 16
// speedup vs baseline: 1.4800x; 1.4800x over previous
#include <cuda_runtime.h>
#include <cuda_fp16.h>
#include <math.h>
#include <stdint.h>

// ---------------- problem constants ----------------
#define B_    32
#define L_    12
#define N_    512
#define D_    128
#define BN_   16384
#define LBN_  196608
#define FK_   256
#define T_    12
#define RES_ELEMS  25165824ULL
#define FORE_ELEMS 50331648ULL

// ---------------- device scratch ----------------
__device__ __half g_Xs    [(size_t)LBN_ * 128];
__device__ __half g_GI    [(size_t)LBN_ * 384];
__device__ __half g_GH    [(size_t)BN_  * 384];
__device__ __half g_rnn   [(size_t)LBN_ * 128];
__device__ __half g_rnnpe [(size_t)LBN_ * 128];
__device__ __half g_QKV   [(size_t)LBN_ * 384];
__device__ __half g_attn  [(size_t)LBN_ * 128];
__device__ __half g_Kc    [(size_t)23 * BN_ * 128];
__device__ __half g_Vc    [(size_t)23 * BN_ * 128];
__device__ __half g_aresU [(size_t)12 * BN_ * 128];   // slot 0 = attn last, 1..11 = decode outs
__device__ __half g_Qbuf  [(size_t)BN_ * 128];
__device__ __half g_GIdec [(size_t)BN_ * 384];
__device__ __half g_GHdec [(size_t)BN_ * 384];
__device__ __half g_g     [(size_t)BN_ * 128];
__device__ __half g_hlast [(size_t)BN_ * 128];
__device__ float  g_pe    [64 * 128];
__device__ float  g_Kpe   [24 * 128];
__device__ float  g_Vpe   [24 * 128];
// fp16 weights
__device__ __half g_wih_h  [49152];
__device__ __half g_whh_h  [49152];
__device__ __half g_inw_h  [49152];
__device__ __half g_Wf     [49152];
__device__ float  g_bf     [384];
__device__ __half g_Wbo    [16384];
__device__ float  g_bbo    [128];
__device__ __half g_Wfo    [32768];
__device__ float  g_ffo    [256];

// ---------------- helpers ----------------
__device__ __forceinline__ void mma16(float c[4], const unsigned a[4],
                                      unsigned b0, unsigned b1) {
    asm volatile(
        "mma.sync.aligned.m16n8k16.row.col.f32.f16.f16.f32 "
        "{%0,%1,%2,%3}, {%4,%5,%6,%7}, {%8,%9}, {%0,%1,%2,%3};\n"
        : "+f"(c[0]), "+f"(c[1]), "+f"(c[2]), "+f"(c[3])
        : "r"(a[0]), "r"(a[1]), "r"(a[2]), "r"(a[3]), "r"(b0), "r"(b1));
}
__device__ __forceinline__ float sigmoid_f(float x) {
    return __fdividef(1.f, 1.f + __expf(-x));
}
__device__ __forceinline__ float tanh_f(float x) {
    float ex = __expf(2.f * x);
    return 1.f - __fdividef(2.f, ex + 1.f);
}

#define CP16(dst, src) asm volatile("cp.async.cg.shared.global [%0], [%1], 16;" :: "r"(dst), "l"(src))

// ---------------- fp16 tensor-core GEMM (m16n8k16), BK=16, 4-stage cp.async ----------------
// C = A[M,128] @ W[N,128]^T + bias. smem rows stride 24 halves (proven conflict-free).
// MODE 0 plain fp16 out. 3 QKV + K/V scatter (N=384). 4 proj: Q + K/V scatter at pos (N=384).
// 6 backcast+LN fused fp32 (N=128). 7 forecast slice at timestep pos (M=BN, N=256).
#define GSTAGE_H 6144
#define GSMEM_BYTES (4 * GSTAGE_H * 2)

template <int MODE>
__global__ __launch_bounds__(256, 2) void gemm3(
    const __half* __restrict__ A, const __half* __restrict__ W,
    const float* __restrict__ bias, void* __restrict__ C,
    int M, int N, int pos,
    __half* __restrict__ Kc, __half* __restrict__ Vc,
    const float* __restrict__ Xg, const float* __restrict__ gammap,
    const float* __restrict__ betap)
{
    extern __shared__ __half smh[];

    const int tid = threadIdx.x, lane = tid & 31, warp = tid >> 5;
    const int wm = (warp >> 2) * 64;
    const int wn = (warp & 3) * 32;
    const int blockM = blockIdx.y * 128;
    const int blockN = blockIdx.x * 128;

    const int arow = tid >> 1;
    const int chunk = tid & 1;
    const __half* Ag = A + (size_t)(blockM + arow) * 128 + chunk * 8;
    const __half* Wg = W + (size_t)(blockN + arow) * 128 + chunk * 8;
    uint32_t smb = (uint32_t)__cvta_generic_to_shared(smh);
    uint32_t a_s0 = smb + (uint32_t)(arow * 24 + chunk * 8) * 2;
    uint32_t w_s0 = smb + (uint32_t)(3072 + arow * 24 + chunk * 8) * 2;

    #define LOADSTAGE(S, KB) do { \
        CP16(a_s0 + (S) * (GSTAGE_H * 2), Ag + (KB)); \
        CP16(w_s0 + (S) * (GSTAGE_H * 2), Wg + (KB)); \
    } while (0)

    float c[4][4][4];
    #pragma unroll
    for (int i = 0; i < 4; i++)
        #pragma unroll
        for (int j = 0; j < 4; j++)
            #pragma unroll
            for (int r = 0; r < 4; r++) c[i][j][r] = 0.f;

    LOADSTAGE(0, 0);
    asm volatile("cp.async.commit_group;");
    LOADSTAGE(1, 16);
    asm volatile("cp.async.commit_group;");
    LOADSTAGE(2, 32);
    asm volatile("cp.async.commit_group;");

    const int kq = (lane & 3) * 2;
    #pragma unroll
    for (int it = 0; it < 8; ++it) {
        asm volatile("cp.async.wait_group 2;");
        __syncthreads();
        if (it + 3 < 8) LOADSTAGE((it + 3) % 4, (it + 3) * 16);
        asm volatile("cp.async.commit_group;");

        const __half* Ab = smh + (it % 4) * GSTAGE_H;
        const __half* Wb = Ab + 3072;
        unsigned af[4][4];
        #pragma unroll
        for (int mt = 0; mt < 4; mt++) {
            int row = wm + mt * 16 + (lane >> 2);
            af[mt][0] = *(const unsigned*)(Ab + row * 24 + kq);
            af[mt][1] = *(const unsigned*)(Ab + (row + 8) * 24 + kq);
            af[mt][2] = *(const unsigned*)(Ab + row * 24 + kq + 8);
            af[mt][3] = *(const unsigned*)(Ab + (row + 8) * 24 + kq + 8);
        }
        #pragma unroll
        for (int nt = 0; nt < 4; nt++) {
            int col = wn + nt * 8 + (lane >> 2);
            unsigned b0 = *(const unsigned*)(Wb + col * 24 + kq);
            unsigned b1 = *(const unsigned*)(Wb + col * 24 + kq + 8);
            #pragma unroll
            for (int mt = 0; mt < 4; mt++)
                mma16(c[mt][nt], af[mt], b0, b1);
        }
    }
    #undef LOADSTAGE

    // ================= epilogues =================
    if (MODE == 6) {
        asm volatile("cp.async.wait_group 0;");
        __syncthreads();
        float* sf = reinterpret_cast<float*>(smh);
        float* ssum = sf;
        float* ssq  = sf + 512;
        float ps[8], pq[8];
        #pragma unroll
        for (int p = 0; p < 8; p++) { ps[p] = 0.f; pq[p] = 0.f; }
        size_t xr[8];
        #pragma unroll
        for (int mt = 0; mt < 4; mt++) {
            int gr0 = blockM + wm + mt * 16 + (lane >> 2);
            int gr1 = gr0 + 8;
            int l0 = gr0 >> 14, r0 = gr0 & 16383;
            xr[mt * 2]     = (((size_t)((r0 >> 9) * 12 + l0) * 512 + (r0 & 511)) << 7);
            int l1 = gr1 >> 14, r1 = gr1 & 16383;
            xr[mt * 2 + 1] = (((size_t)((r1 >> 9) * 12 + l1) * 512 + (r1 & 511)) << 7);
            #pragma unroll
            for (int nt = 0; nt < 4; nt++) {
                int gc = wn + nt * 8 + 2 * (lane & 3);
                float bv0 = bias[gc], bv1 = bias[gc + 1];
                float u00 = Xg[xr[mt*2]   + gc]     - fmaxf(c[mt][nt][0] + bv0, 0.f);
                float u01 = Xg[xr[mt*2]   + gc + 1] - fmaxf(c[mt][nt][1] + bv1, 0.f);
                float u10 = Xg[xr[mt*2+1] + gc]     - fmaxf(c[mt][nt][2] + bv0, 0.f);
                float u11 = Xg[xr[mt*2+1] + gc + 1] - fmaxf(c[mt][nt][3] + bv1, 0.f);
                c[mt][nt][0] = u00; c[mt][nt][1] = u01;
                c[mt][nt][2] = u10; c[mt][nt][3] = u11;
                ps[mt*2]   += u00 + u01;  pq[mt*2]   += u00*u00 + u01*u01;
                ps[mt*2+1] += u10 + u11;  pq[mt*2+1] += u10*u10 + u11*u11;
            }
        }
        #pragma unroll
        for (int o = 1; o < 4; o <<= 1) {
            #pragma unroll
            for (int p = 0; p < 8; p++) {
                ps[p] += __shfl_xor_sync(0xffffffffu, ps[p], o);
                pq[p] += __shfl_xor_sync(0xffffffffu, pq[p], o);
            }
        }
        int wnIdx = warp & 3;
        if ((lane & 3) == 0) {
            #pragma unroll
            for (int mt = 0; mt < 4; mt++) {
                int lr = wm + mt * 16 + (lane >> 2);
                ssum[wnIdx * 128 + lr]     = ps[mt*2];
                ssq [wnIdx * 128 + lr]     = pq[mt*2];
                ssum[wnIdx * 128 + lr + 8] = ps[mt*2+1];
                ssq [wnIdx * 128 + lr + 8] = pq[mt*2+1];
            }
        }
        __syncthreads();
        float* Cf = (float*)C;
        #pragma unroll
        for (int mt = 0; mt < 4; mt++) {
            int lr0 = wm + mt * 16 + (lane >> 2);
            int lr1 = lr0 + 8;
            float s0 = ssum[lr0] + ssum[128+lr0] + ssum[256+lr0] + ssum[384+lr0];
            float q0 = ssq[lr0]  + ssq[128+lr0]  + ssq[256+lr0]  + ssq[384+lr0];
            float s1 = ssum[lr1] + ssum[128+lr1] + ssum[256+lr1] + ssum[384+lr1];
            float q1 = ssq[lr1]  + ssq[128+lr1]  + ssq[256+lr1]  + ssq[384+lr1];
            float mu0 = s0 * (1.f/128.f);
            float iv0 = rsqrtf(q0 * (1.f/128.f) - mu0*mu0 + 1e-5f);
            float mu1 = s1 * (1.f/128.f);
            float iv1 = rsqrtf(q1 * (1.f/128.f) - mu1*mu1 + 1e-5f);
            #pragma unroll
            for (int nt = 0; nt < 4; nt++) {
                int gc = wn + nt * 8 + 2 * (lane & 3);
                float g0 = gammap[gc], g1 = gammap[gc+1];
                float b0 = betap[gc],  b1 = betap[gc+1];
                Cf[xr[mt*2]   + gc]     = (c[mt][nt][0] - mu0) * iv0 * g0 + b0;
                Cf[xr[mt*2]   + gc + 1] = (c[mt][nt][1] - mu0) * iv0 * g1 + b1;
                Cf[xr[mt*2+1] + gc]     = (c[mt][nt][2] - mu1) * iv1 * g0 + b0;
                Cf[xr[mt*2+1] + gc + 1] = (c[mt][nt][3] - mu1) * iv1 * g1 + b1;
            }
        }
        return;
    }

    #pragma unroll
    for (int mt = 0; mt < 4; mt++) {
        #pragma unroll
        for (int nt = 0; nt < 4; nt++) {
            int gr = blockM + wm + mt * 16 + (lane >> 2);
            int gc = blockN + wn + nt * 8 + 2 * (lane & 3);
            float bv0 = bias[gc], bv1 = bias[gc + 1];
            float v00 = c[mt][nt][0] + bv0, v01 = c[mt][nt][1] + bv1;
            float v10 = c[mt][nt][2] + bv0, v11 = c[mt][nt][3] + bv1;
            int gr1 = gr + 8;
            __half2 h0 = __floats2half2_rn(v00, v01);
            __half2 h1 = __floats2half2_rn(v10, v11);
            if (MODE == 0) {
                __half* Ch = (__half*)C;
                *(__half2*)(Ch + (size_t)gr * N + gc)  = h0;
                *(__half2*)(Ch + (size_t)gr1 * N + gc) = h1;
            } else if (MODE == 7) {
                float* Cf = (float*)C;
                size_t or0 = (size_t)((gr  >> 9) * 12 + pos) * 512 + (gr  & 511);
                size_t or1 = (size_t)((gr1 >> 9) * 12 + pos) * 512 + (gr1 & 511);
                float* p0 = Cf + or0 * 256 + gc;
                float* p1 = Cf + or1 * 256 + gc;
                p0[0] = v00; p0[1] = v01; p1[0] = v10; p1[1] = v11;
            } else if (MODE == 3) {
                __half* Ch = (__half*)C;
                *(__half2*)(Ch + (size_t)gr * N + gc)  = h0;
                *(__half2*)(Ch + (size_t)gr1 * N + gc) = h1;
                if (gc >= 128 && gc < 256) {
                    *(__half2*)(Kc + (size_t)gr * 128 + gc - 128)  = h0;
                    *(__half2*)(Kc + (size_t)gr1 * 128 + gc - 128) = h1;
                } else if (gc >= 256) {
                    *(__half2*)(Vc + (size_t)gr * 128 + gc - 256)  = h0;
                    *(__half2*)(Vc + (size_t)gr1 * 128 + gc - 256) = h1;
                }
            } else { // MODE 4
                __half* Ch = (__half*)C;
                if (gc < 128) {
                    *(__half2*)(Ch + (size_t)gr * 128 + gc)  = h0;
                    *(__half2*)(Ch + (size_t)gr1 * 128 + gc) = h1;
                } else if (gc < 256) {
                    *(__half2*)(Kc + ((size_t)pos * BN_ + gr) * 128 + gc - 128)  = h0;
                    *(__half2*)(Kc + ((size_t)pos * BN_ + gr1) * 128 + gc - 128) = h1;
                } else {
                    *(__half2*)(Vc + ((size_t)pos * BN_ + gr) * 128 + gc - 256)  = h0;
                    *(__half2*)(Vc + ((size_t)pos * BN_ + gr1) * 128 + gc - 256) = h1;
                }
            }
        }
    }
}

// ---------------- prep kernels ----------------
__global__ void pe_init_kernel(float* pe) {
    int idx = blockIdx.x * blockDim.x + threadIdx.x;
    if (idx >= 64 * 128) return;
    int pos = idx >> 7, d = idx & 127;
    int j = d >> 1;
    float div = expf((float)(2 * j) * (-logf(10000.f) / 128.f));
    float ang = (float)pos * div;
    pe[idx] = (d & 1) ? cosf(ang) : sinf(ang);
}

__global__ void halfw_a_kernel(const float* __restrict__ w_ih, const float* __restrict__ w_hh,
                               const float* __restrict__ in_w,
                               __half* wih, __half* whh, __half* inw) {
    int i = blockIdx.x * blockDim.x + threadIdx.x;
    if (i < 49152)       wih[i]         = __float2half(w_ih[i]);
    else if (i < 98304)  whh[i - 49152] = __float2half(w_hh[i - 49152]);
    else if (i < 147456) inw[i - 98304] = __float2half(in_w[i - 98304]);
}

__global__ void xconv_kernel(const float* __restrict__ X, __half* __restrict__ Xs) {
    int idx = blockIdx.x * blockDim.x + threadIdx.x;
    if (idx >= LBN_ * 32) return;
    int d4 = (idx & 31) * 4;
    int row = idx >> 5;
    int l = row >> 14, rem = row & 16383, b = rem >> 9, n = rem & 511;
    float4 v = *(const float4*)(X + (((size_t)(b * 12 + l) * 512 + n) << 7) + d4);
    *(__half2*)(Xs + (size_t)row * 128 + d4)     = __floats2half2_rn(v.x, v.y);
    *(__half2*)(Xs + (size_t)row * 128 + d4 + 2) = __floats2half2_rn(v.z, v.w);
}

__global__ void prefuse_kernel(const float* __restrict__ W1, const float* __restrict__ W2,
                               const float* __restrict__ b2, const float* __restrict__ b1,
                               __half* __restrict__ Wout, float* __restrict__ bout, int R) {
    int idx = blockIdx.x * blockDim.x + threadIdx.x;
    if (idx >= R * 128) return;
    int r = idx >> 7, k = idx & 127;
    float acc = 0.f;
    #pragma unroll 4
    for (int j = 0; j < 128; j++) acc += W1[r * 128 + j] * W2[j * 128 + k];
    Wout[idx] = __float2half(acc);
    if (k == 0) {
        float b = 0.f;
        for (int j = 0; j < 128; j++) b += W1[r * 128 + j] * b2[j];
        bout[r] = b + (b1 ? b1[r] : 0.f);
    }
}

__global__ void kvpe_kernel(const float* __restrict__ attn_in_w, const float* __restrict__ pe,
                            float* __restrict__ Kpe, float* __restrict__ Vpe) {
    int idx = blockIdx.x * blockDim.x + threadIdx.x;
    if (idx >= 24 * 256) return;
    int pos = idx >> 8, c = idx & 255;
    const float* wrow = attn_in_w + (size_t)(128 + c) * 128;
    const float* prow = pe + pos * 128;
    float acc = 0.f;
    #pragma unroll 4
    for (int d = 0; d < 128; d++) acc += wrow[d] * prow[d];
    if (c < 128) Kpe[pos * 128 + c] = acc;
    else         Vpe[pos * 128 + (c - 128)] = acc;
}

// ---------------- GRU gates (fp16 I/O, half2-vectorized) ----------------
__global__ void gru_gates_kernel(const __half* __restrict__ gi, const __half* __restrict__ gh,
                                 const __half* __restrict__ h, __half* __restrict__ hnew,
                                 __half* __restrict__ hnext, const float* __restrict__ pe_row,
                                 const float* __restrict__ bhh, int total2) {
    int idx = blockIdx.x * blockDim.x + threadIdx.x;
    if (idx >= total2) return;
    int row = idx >> 6, d2 = (idx & 63) * 2;
    size_t b3 = (size_t)row * 384;
    float2 ir  = __half22float2(*(const __half2*)(gi + b3 + d2));
    float2 iz  = __half22float2(*(const __half2*)(gi + b3 + 128 + d2));
    float2 in_ = __half22float2(*(const __half2*)(gi + b3 + 256 + d2));
    float2 hr, hz, hn;
    if (gh) {
        hr = __half22float2(*(const __half2*)(gh + b3 + d2));
        hz = __half22float2(*(const __half2*)(gh + b3 + 128 + d2));
        hn = __half22float2(*(const __half2*)(gh + b3 + 256 + d2));
    } else {
        hr = make_float2(bhh[d2], bhh[d2 + 1]);
        hz = make_float2(bhh[128 + d2], bhh[128 + d2 + 1]);
        hn = make_float2(bhh[256 + d2], bhh[256 + d2 + 1]);
    }
    float2 hv = h ? __half22float2(*(const __half2*)(h + (size_t)row * 128 + d2))
                  : make_float2(0.f, 0.f);
    float r0 = sigmoid_f(ir.x + hr.x), r1 = sigmoid_f(ir.y + hr.y);
    float z0 = sigmoid_f(iz.x + hz.x), z1 = sigmoid_f(iz.y + hz.y);
    float n0 = tanh_f(in_.x + r0 * hn.x), n1 = tanh_f(in_.y + r1 * hn.y);
    float o0 = (1.f - z0) * n0 + z0 * hv.x;
    float o1 = (1.f - z1) * n1 + z1 * hv.y;
    *(__half2*)(hnew + (size_t)row * 128 + d2) = __floats2half2_rn(o0, o1);
    if (hnext)
        *(__half2*)(hnext + (size_t)row * 128 + d2) =
            __floats2half2_rn(o0 + pe_row[d2], o1 + pe_row[d2 + 1]);
}

// ---------------- encoder self-attention ----------------
__global__ void enc_attn_kernel(const __half* __restrict__ QKV, __half* __restrict__ O,
                                __half* __restrict__ ares0) {
    int bn = blockIdx.x;
    int w = threadIdx.x >> 5, lane = threadIdx.x & 31;
    __shared__ float q[4][12][32];
    __shared__ float k[4][12][33];
    __shared__ float v[4][12][33];
    __shared__ float s[4][12][13];

    for (int e = lane; e < 12 * 16; e += 32) {
        int l = e >> 4, d2 = (e & 15) * 2;
        size_t base = ((size_t)l * BN_ + bn) * 384 + w * 32 + d2;
        float2 qv = __half22float2(*(const __half2*)(QKV + base));
        float2 kv = __half22float2(*(const __half2*)(QKV + base + 128));
        float2 vv = __half22float2(*(const __half2*)(QKV + base + 256));
        q[w][l][d2] = qv.x; q[w][l][d2+1] = qv.y;
        k[w][l][d2] = kv.x; k[w][l][d2+1] = kv.y;
        v[w][l][d2] = vv.x; v[w][l][d2+1] = vv.y;
    }
    __syncwarp();
    const float scale = 0.17677669529663687f;
    if (lane < 12) {
        int j = lane;
        #pragma unroll
        for (int i = 0; i < 12; i++) {
            float acc = 0.f;
            #pragma unroll
            for (int d = 0; d < 32; d++) acc += q[w][i][d] * k[w][j][d];
            s[w][i][j] = acc * scale;
        }
    }
    __syncwarp();
    if (lane < 12) {
        int i = lane;
        float mx = -1e30f;
        #pragma unroll
        for (int j = 0; j < 12; j++) mx = fmaxf(mx, s[w][i][j]);
        float sum = 0.f;
        #pragma unroll
        for (int j = 0; j < 12; j++) { float e = __expf(s[w][i][j] - mx); s[w][i][j] = e; sum += e; }
        float inv = __fdividef(1.f, sum);
        #pragma unroll
        for (int j = 0; j < 12; j++) s[w][i][j] *= inv;
    }
    __syncwarp();
    {
        int d = lane;
        #pragma unroll
        for (int i = 0; i < 12; i++) {
            float acc = 0.f;
            #pragma unroll
            for (int j = 0; j < 12; j++) acc += s[w][i][j] * v[w][j][d];
            __half hv = __float2half(acc);
            O[((size_t)i * BN_ + bn) * 128 + w * 32 + d] = hv;
            if (i == 11) ares0[(size_t)bn * 128 + w * 32 + d] = hv;
        }
    }
}

// ---------------- decode attention (fp16 KV/Q, PE-drift multipliers) ----------------
__global__ void dec_attn_kernel(const __half* __restrict__ Qbuf,
                                const __half* __restrict__ Kc, const __half* __restrict__ Vc,
                                const float* __restrict__ Kpe, const float* __restrict__ Vpe,
                                __half* __restrict__ O, int t) {
    int len = 12 + t;
    int bn = blockIdx.x;
    int w = threadIdx.x >> 5, lane = threadIdx.x & 31;
    __shared__ float qs[4][32];
    __shared__ float Kb[4][23][33];
    __shared__ float Vb[4][23][33];
    __shared__ float aw[4][23];

    qs[w][lane] = __half2float(Qbuf[(size_t)bn * 128 + w * 32 + lane]);
    for (int e = lane; e < len * 16; e += 32) {
        int i = e >> 4, d2 = (e & 15) * 2;
        size_t src = ((size_t)i * BN_ + bn) * 128 + w * 32 + d2;
        float2 kv = __half22float2(*(const __half2*)(Kc + src));
        float2 vv = __half22float2(*(const __half2*)(Vc + src));
        Kb[w][i][d2] = kv.x; Kb[w][i][d2+1] = kv.y;
        Vb[w][i][d2] = vv.x; Vb[w][i][d2+1] = vv.y;
    }
    __syncwarp();

    float sc = -1e30f;
    int i = lane;
    if (i < len) {
        float m = (i < 12) ? (float)(t - 1) : (float)(t - i + 12);
        float a = 0.f, ap = 0.f;
        #pragma unroll
        for (int d = 0; d < 32; d++) {
            float qd = qs[w][d];
            a  += Kb[w][i][d] * qd;
            ap += Kpe[i * 128 + w * 32 + d] * qd;
        }
        sc = (a + m * ap) * 0.17677669529663687f;
    }
    float mx = sc;
    #pragma unroll
    for (int o = 16; o > 0; o >>= 1) mx = fmaxf(mx, __shfl_xor_sync(0xffffffffu, mx, o));
    float e = (i < len) ? __expf(sc - mx) : 0.f;
    float sum = e;
    #pragma unroll
    for (int o = 16; o > 0; o >>= 1) sum += __shfl_xor_sync(0xffffffffu, sum, o);
    float a = __fdividef(e, sum);
    if (i < len) aw[w][i] = a;
    __syncwarp();

    int d = lane;
    float acc = 0.f;
    for (int j = 0; j < len; j++) {
        float mj = (j < 12) ? (float)(t - 1) : (float)(t - j + 12);
        acc += aw[w][j] * (Vb[w][j][d] + mj * Vpe[j * 128 + w * 32 + d]);
    }
    O[(size_t)bn * 128 + w * 32 + d] = __float2half(acc);
}

// ---------------- host ----------------
static inline float* symaddr(const void* sym) {
    void* p = nullptr;
    cudaGetSymbolAddress(&p, sym);
    return (float*)p;
}
static inline __half* symaddr_h(const void* sym) {
    void* p = nullptr;
    cudaGetSymbolAddress(&p, sym);
    return (__half*)p;
}

template <int MODE>
static inline void launch_gemm(cudaStream_t st,
                               const __half* A, const __half* W, const float* b, void* C,
                               int M, int N, int pos = 0,
                               __half* Kc = nullptr, __half* Vc = nullptr,
                               const float* Xg = nullptr,
                               const float* gam = nullptr, const float* bet = nullptr) {
    gemm3<MODE><<<dim3(N / 128, M / 128, 1), 256, GSMEM_BYTES, st>>>(
        A, W, b, C, M, N, pos, Kc, Vc, Xg, gam, bet);
}

extern "C" void kernel_launch(void* const* d_in, const int* in_sizes, int n_in,
                              void* d_out, int out_size) {
    const float* X          = (const float*)d_in[0];
    const float* gru_w_ih   = (const float*)d_in[1];
    const float* gru_w_hh   = (const float*)d_in[2];
    const float* gru_b_ih   = (const float*)d_in[3];
    const float* gru_b_hh   = (const float*)d_in[4];
    const float* attn_in_w  = (const float*)d_in[5];
    const float* attn_in_b  = (const float*)d_in[6];
    const float* attn_out_w = (const float*)d_in[7];
    const float* attn_out_b = (const float*)d_in[8];
    const float* backcast_w = (const float*)d_in[9];
    const float* backcast_b = (const float*)d_in[10];
    const float* forecast_w = (const float*)d_in[11];
    const float* forecast_b = (const float*)d_in[12];
    const float* ln_gamma   = (const float*)d_in[13];
    const float* ln_beta    = (const float*)d_in[14];

    float* out  = (float*)d_out;
    float* res  = out;
    float* fore = out + RES_ELEMS;

    __half* Xs     = symaddr_h(g_Xs);
    __half* GI     = symaddr_h(g_GI);
    __half* GH     = symaddr_h(g_GH);
    __half* rnn    = symaddr_h(g_rnn);
    __half* rnnpe  = symaddr_h(g_rnnpe);
    __half* QKV    = symaddr_h(g_QKV);
    __half* attn   = symaddr_h(g_attn);
    __half* Kc     = symaddr_h(g_Kc);
    __half* Vc     = symaddr_h(g_Vc);
    __half* aresU  = symaddr_h(g_aresU);
    __half* Qbuf   = symaddr_h(g_Qbuf);
    __half* GIdec  = symaddr_h(g_GIdec);
    __half* GHdec  = symaddr_h(g_GHdec);
    __half* gbuf   = symaddr_h(g_g);
    __half* hlast  = symaddr_h(g_hlast);
    float*  pe     = symaddr(g_pe);
    float*  Kpe    = symaddr(g_Kpe);
    float*  Vpe    = symaddr(g_Vpe);
    __half* wih_h  = symaddr_h(g_wih_h);
    __half* whh_h  = symaddr_h(g_whh_h);
    __half* inw_h  = symaddr_h(g_inw_h);
    __half* Wf     = symaddr_h(g_Wf);
    float*  bf     = symaddr(g_bf);
    __half* Wbo    = symaddr_h(g_Wbo);
    float*  bbo    = symaddr(g_bbo);
    __half* Wfo    = symaddr_h(g_Wfo);
    float*  ffo    = symaddr(g_ffo);

    static bool inited = false;
    static cudaStream_t s2 = 0, s3 = 0;
    static cudaEvent_t evF = 0, evB1 = 0, evEnc = 0, evM1 = 0, evW = 0, evS3 = 0;
    static cudaEvent_t evGH[13], evGate[13], evA[12];
    if (!inited) {
        cudaFuncSetAttribute(gemm3<0>, cudaFuncAttributeMaxDynamicSharedMemorySize, GSMEM_BYTES);
        cudaFuncSetAttribute(gemm3<3>, cudaFuncAttributeMaxDynamicSharedMemorySize, GSMEM_BYTES);
        cudaFuncSetAttribute(gemm3<4>, cudaFuncAttributeMaxDynamicSharedMemorySize, GSMEM_BYTES);
        cudaFuncSetAttribute(gemm3<6>, cudaFuncAttributeMaxDynamicSharedMemorySize, GSMEM_BYTES);
        cudaFuncSetAttribute(gemm3<7>, cudaFuncAttributeMaxDynamicSharedMemorySize, GSMEM_BYTES);
        cudaStreamCreateWithFlags(&s2, cudaStreamNonBlocking);
        cudaStreamCreateWithFlags(&s3, cudaStreamNonBlocking);
        cudaEventCreateWithFlags(&evF,   cudaEventDisableTiming);
        cudaEventCreateWithFlags(&evB1,  cudaEventDisableTiming);
        cudaEventCreateWithFlags(&evEnc, cudaEventDisableTiming);
        cudaEventCreateWithFlags(&evM1,  cudaEventDisableTiming);
        cudaEventCreateWithFlags(&evW,   cudaEventDisableTiming);
        cudaEventCreateWithFlags(&evS3,  cudaEventDisableTiming);
        for (int i = 0; i < 13; i++) {
            cudaEventCreateWithFlags(&evGH[i],   cudaEventDisableTiming);
            cudaEventCreateWithFlags(&evGate[i], cudaEventDisableTiming);
        }
        for (int i = 0; i < 12; i++)
            cudaEventCreateWithFlags(&evA[i], cudaEventDisableTiming);
        inited = true;
    }

    const int TPB = 256;
    const cudaStream_t s0 = 0;

    // ---- s0 prep (evF recorded first so side streams can fork legally) ----
    pe_init_kernel<<<(64 * 128 + TPB - 1) / TPB, TPB, 0, s0>>>(pe);
    cudaEventRecord(evF, s0);
    halfw_a_kernel<<<(147456 + TPB - 1) / TPB, TPB, 0, s0>>>(gru_w_ih, gru_w_hh, attn_in_w,
                                                             wih_h, whh_h, inw_h);
    xconv_kernel<<<LBN_ * 32 / TPB, TPB, 0, s0>>>(X, Xs);

    // ---- s3: fork off evF, weight prefusions ----
    cudaStreamWaitEvent(s3, evF, 0);
    prefuse_kernel<<<(49152 + TPB - 1) / TPB, TPB, 0, s3>>>(gru_w_ih, attn_out_w, attn_out_b,
                                                            gru_b_ih, Wf, bf, 384);
    prefuse_kernel<<<(16384 + TPB - 1) / TPB, TPB, 0, s3>>>(backcast_w, attn_out_w, attn_out_b,
                                                            backcast_b, Wbo, bbo, 128);
    prefuse_kernel<<<(32768 + TPB - 1) / TPB, TPB, 0, s3>>>(forecast_w, attn_out_w, attn_out_b,
                                                            forecast_b, Wfo, ffo, 256);
    cudaEventRecord(evW, s3);

    // ---- s2: fork off evF, kvpe ----
    cudaStreamWaitEvent(s2, evF, 0);
    kvpe_kernel<<<(24 * 256 + TPB - 1) / TPB, TPB, 0, s2>>>(attn_in_w, pe, Kpe, Vpe);
    cudaEventRecord(evB1, s2);

    // ---- GI for all encoder steps ----
    launch_gemm<0>(s0, Xs, wih_h, gru_b_ih, GI, LBN_, 384);

    // ---- GRU encode ----
    gru_gates_kernel<<<BN_ * 64 / TPB, TPB, 0, s0>>>(GI, nullptr, nullptr,
                                                     rnn, rnnpe, pe, gru_b_hh, BN_ * 64);
    for (int l = 1; l < 12; l++) {
        launch_gemm<0>(s0, rnn + (size_t)(l - 1) * BN_ * 128, whh_h, gru_b_hh, GH, BN_, 384);
        gru_gates_kernel<<<BN_ * 64 / TPB, TPB, 0, s0>>>(GI + (size_t)l * BN_ * 384, GH,
                                                         rnn + (size_t)(l - 1) * BN_ * 128,
                                                         rnn + (size_t)l * BN_ * 128,
                                                         rnnpe + (size_t)l * BN_ * 128,
                                                         pe + l * 128, nullptr, BN_ * 64);
    }
    cudaEventRecord(evEnc, s0);

    // ---- s2: GH_1 (needs rnn[11] only) ----
    cudaStreamWaitEvent(s2, evEnc, 0);
    launch_gemm<0>(s2, rnn + (size_t)11 * BN_ * 128, whh_h, gru_b_hh, GHdec, BN_, 384);
    cudaEventRecord(evGH[1], s2);

    // ---- encoder MHA ----
    launch_gemm<3>(s0, rnnpe, inw_h, attn_in_b, QKV, LBN_, 384, 0, Kc, Vc);
    enc_attn_kernel<<<BN_, 128, 0, s0>>>(QKV, attn, aresU);
    cudaEventRecord(evM1, s0);
    cudaEventRecord(evA[0], s0);

    // ---- s3: backcast + LN, then forecast slices as they become ready ----
    cudaStreamWaitEvent(s3, evM1, 0);
    launch_gemm<6>(s3, attn, Wbo, bbo, res, LBN_, 128, 0, nullptr, nullptr,
                   X, ln_gamma, ln_beta);
    cudaStreamWaitEvent(s3, evA[0], 0);
    launch_gemm<7>(s3, aresU, Wfo, ffo, fore, BN_, 256, 0);

    // ---- GI_1 (prefused Wf, A = aresU[0] = attn last) ----
    cudaStreamWaitEvent(s0, evW, 0);
    launch_gemm<0>(s0, aresU, Wf, bf, GIdec, BN_, 384);

    // ---- decode loop: gates -> proj -> attn -> GI_{t+1} on s0; GH on s2; fore slices on s3 ----
    cudaStreamWaitEvent(s0, evB1, 0);
    const __half* hl = rnn + (size_t)11 * BN_ * 128;
    for (int t = 1; t <= 11; t++) {
        cudaStreamWaitEvent(s0, evGH[t], 0);
        gru_gates_kernel<<<BN_ * 64 / TPB, TPB, 0, s0>>>(GIdec, GHdec, hl, gbuf,
                                                         hlast, pe + (11 + t) * 128,
                                                         nullptr, BN_ * 64);
        hl = hlast;
        if (t < 11) {
            cudaEventRecord(evGate[t], s0);
            cudaStreamWaitEvent(s2, evGate[t], 0);
            launch_gemm<0>(s2, hlast, whh_h, gru_b_hh, GHdec, BN_, 384);
            cudaEventRecord(evGH[t + 1], s2);
        }
        launch_gemm<4>(s0, gbuf, inw_h, attn_in_b, Qbuf, BN_, 384, 11 + t, Kc, Vc);
        dec_attn_kernel<<<BN_, 128, 0, s0>>>(Qbuf, Kc, Vc, Kpe, Vpe,
                                             aresU + (size_t)t * BN_ * 128, t);
        if (t < 11) {
            cudaEventRecord(evA[t], s0);
            cudaStreamWaitEvent(s3, evA[t], 0);
            launch_gemm<7>(s3, aresU + (size_t)t * BN_ * 128, Wfo, ffo, fore, BN_, 256, t);
            launch_gemm<0>(s0, aresU + (size_t)t * BN_ * 128, Wf, bf, GIdec, BN_, 384);
        }
    }
    cudaEventRecord(evS3, s3);

    // ---- tail: last forecast slice on s0, join s3 ----
    cudaStreamWaitEvent(s0, evS3, 0);
    launch_gemm<7>(s0, aresU + (size_t)11 * BN_ * 128, Wfo, ffo, fore, BN_, 256, 11);
}

// round 17
// speedup vs baseline: 1.4854x; 1.0036x over previous
#include <cuda_runtime.h>
#include <cuda_fp16.h>
#include <math.h>
#include <stdint.h>

// ---------------- problem constants ----------------
#define B_    32
#define L_    12
#define N_    512
#define D_    128
#define BN_   16384
#define LBN_  196608
#define FK_   256
#define T_    12
#define RES_ELEMS  25165824ULL
#define FORE_ELEMS 50331648ULL

// ---------------- device scratch ----------------
__device__ __half g_Xs    [(size_t)LBN_ * 128];
__device__ __half g_GI    [(size_t)LBN_ * 384];
__device__ __half g_GH    [(size_t)BN_  * 384];
__device__ __half g_rnn   [(size_t)LBN_ * 128];
__device__ __half g_rnnpe [(size_t)LBN_ * 128];
__device__ __half g_QKV   [(size_t)LBN_ * 384];
__device__ __half g_attn  [(size_t)LBN_ * 128];
__device__ __half g_Kc    [(size_t)23 * BN_ * 128];
__device__ __half g_Vc    [(size_t)23 * BN_ * 128];
__device__ __half g_aresU [(size_t)12 * BN_ * 128];   // slot 0 = attn last, 1..11 = decode outs
__device__ __half g_Qbuf  [(size_t)BN_ * 128];
__device__ __half g_GIdec [(size_t)BN_ * 384];
__device__ __half g_GHdec [(size_t)BN_ * 384];
__device__ __half g_g     [(size_t)BN_ * 128];
__device__ __half g_hlast [(size_t)BN_ * 128];
__device__ float  g_pe    [64 * 128];
__device__ float  g_Kpe   [24 * 128];
__device__ float  g_Vpe   [24 * 128];
// fp16 weights
__device__ __half g_wih_h  [49152];
__device__ __half g_whh_h  [49152];
__device__ __half g_inw_h  [49152];
__device__ __half g_Wf     [49152];
__device__ float  g_bf     [384];
__device__ __half g_Wbo    [16384];
__device__ float  g_bbo    [128];
__device__ __half g_Wfo    [32768];
__device__ float  g_ffo    [256];

// ---------------- helpers ----------------
__device__ __forceinline__ void mma16(float c[4], const unsigned a[4],
                                      unsigned b0, unsigned b1) {
    asm volatile(
        "mma.sync.aligned.m16n8k16.row.col.f32.f16.f16.f32 "
        "{%0,%1,%2,%3}, {%4,%5,%6,%7}, {%8,%9}, {%0,%1,%2,%3};\n"
        : "+f"(c[0]), "+f"(c[1]), "+f"(c[2]), "+f"(c[3])
        : "r"(a[0]), "r"(a[1]), "r"(a[2]), "r"(a[3]), "r"(b0), "r"(b1));
}
__device__ __forceinline__ float sigmoid_f(float x) {
    return __fdividef(1.f, 1.f + __expf(-x));
}
__device__ __forceinline__ float tanh_f(float x) {
    float ex = __expf(2.f * x);
    return 1.f - __fdividef(2.f, ex + 1.f);
}

#define CP16(dst, src) asm volatile("cp.async.cg.shared.global [%0], [%1], 16;" :: "r"(dst), "l"(src))

// ---------------- fp16 tensor-core GEMM (m16n8k16), BK=16, 3-stage cp.async ----------------
// C = A[M,128] @ W[N,128]^T + bias. smem rows stride 24 halves (proven conflict-free).
// MODE 0 plain fp16 out. 3 QKV + K/V scatter (N=384). 4 proj: Q + K/V scatter at pos (N=384).
// 6 backcast+LN fused fp32 (N=128). 7 forecast slice at timestep pos (M=BN, N=256).
#define GSTAGE_H 6144
#define GSMEM_BYTES (3 * GSTAGE_H * 2)

template <int MODE>
__global__ __launch_bounds__(256, 2) void gemm3(
    const __half* __restrict__ A, const __half* __restrict__ W,
    const float* __restrict__ bias, void* __restrict__ C,
    int M, int N, int pos,
    __half* __restrict__ Kc, __half* __restrict__ Vc,
    const float* __restrict__ Xg, const float* __restrict__ gammap,
    const float* __restrict__ betap)
{
    extern __shared__ __half smh[];

    const int tid = threadIdx.x, lane = tid & 31, warp = tid >> 5;
    const int wm = (warp >> 2) * 64;
    const int wn = (warp & 3) * 32;
    const int blockM = blockIdx.y * 128;
    const int blockN = blockIdx.x * 128;

    const int arow = tid >> 1;
    const int chunk = tid & 1;
    const __half* Ag = A + (size_t)(blockM + arow) * 128 + chunk * 8;
    const __half* Wg = W + (size_t)(blockN + arow) * 128 + chunk * 8;
    uint32_t smb = (uint32_t)__cvta_generic_to_shared(smh);
    uint32_t a_s0 = smb + (uint32_t)(arow * 24 + chunk * 8) * 2;
    uint32_t w_s0 = smb + (uint32_t)(3072 + arow * 24 + chunk * 8) * 2;

    #define LOADSTAGE(S, KB) do { \
        CP16(a_s0 + (S) * (GSTAGE_H * 2), Ag + (KB)); \
        CP16(w_s0 + (S) * (GSTAGE_H * 2), Wg + (KB)); \
    } while (0)

    float c[4][4][4];
    #pragma unroll
    for (int i = 0; i < 4; i++)
        #pragma unroll
        for (int j = 0; j < 4; j++)
            #pragma unroll
            for (int r = 0; r < 4; r++) c[i][j][r] = 0.f;

    LOADSTAGE(0, 0);
    asm volatile("cp.async.commit_group;");
    LOADSTAGE(1, 16);
    asm volatile("cp.async.commit_group;");

    const int kq = (lane & 3) * 2;
    #pragma unroll
    for (int it = 0; it < 8; ++it) {
        asm volatile("cp.async.wait_group 1;");
        __syncthreads();
        if (it + 2 < 8) LOADSTAGE((it + 2) % 3, (it + 2) * 16);
        asm volatile("cp.async.commit_group;");

        const __half* Ab = smh + (it % 3) * GSTAGE_H;
        const __half* Wb = Ab + 3072;
        unsigned af[4][4];
        #pragma unroll
        for (int mt = 0; mt < 4; mt++) {
            int row = wm + mt * 16 + (lane >> 2);
            af[mt][0] = *(const unsigned*)(Ab + row * 24 + kq);
            af[mt][1] = *(const unsigned*)(Ab + (row + 8) * 24 + kq);
            af[mt][2] = *(const unsigned*)(Ab + row * 24 + kq + 8);
            af[mt][3] = *(const unsigned*)(Ab + (row + 8) * 24 + kq + 8);
        }
        #pragma unroll
        for (int nt = 0; nt < 4; nt++) {
            int col = wn + nt * 8 + (lane >> 2);
            unsigned b0 = *(const unsigned*)(Wb + col * 24 + kq);
            unsigned b1 = *(const unsigned*)(Wb + col * 24 + kq + 8);
            #pragma unroll
            for (int mt = 0; mt < 4; mt++)
                mma16(c[mt][nt], af[mt], b0, b1);
        }
    }
    #undef LOADSTAGE

    // ================= epilogues =================
    if (MODE == 6) {
        asm volatile("cp.async.wait_group 0;");
        __syncthreads();
        float* sf = reinterpret_cast<float*>(smh);
        float* ssum = sf;
        float* ssq  = sf + 512;
        float ps[8], pq[8];
        #pragma unroll
        for (int p = 0; p < 8; p++) { ps[p] = 0.f; pq[p] = 0.f; }
        size_t xr[8];
        #pragma unroll
        for (int mt = 0; mt < 4; mt++) {
            int gr0 = blockM + wm + mt * 16 + (lane >> 2);
            int gr1 = gr0 + 8;
            int l0 = gr0 >> 14, r0 = gr0 & 16383;
            xr[mt * 2]     = (((size_t)((r0 >> 9) * 12 + l0) * 512 + (r0 & 511)) << 7);
            int l1 = gr1 >> 14, r1 = gr1 & 16383;
            xr[mt * 2 + 1] = (((size_t)((r1 >> 9) * 12 + l1) * 512 + (r1 & 511)) << 7);
            #pragma unroll
            for (int nt = 0; nt < 4; nt++) {
                int gc = wn + nt * 8 + 2 * (lane & 3);
                float bv0 = bias[gc], bv1 = bias[gc + 1];
                float u00 = Xg[xr[mt*2]   + gc]     - fmaxf(c[mt][nt][0] + bv0, 0.f);
                float u01 = Xg[xr[mt*2]   + gc + 1] - fmaxf(c[mt][nt][1] + bv1, 0.f);
                float u10 = Xg[xr[mt*2+1] + gc]     - fmaxf(c[mt][nt][2] + bv0, 0.f);
                float u11 = Xg[xr[mt*2+1] + gc + 1] - fmaxf(c[mt][nt][3] + bv1, 0.f);
                c[mt][nt][0] = u00; c[mt][nt][1] = u01;
                c[mt][nt][2] = u10; c[mt][nt][3] = u11;
                ps[mt*2]   += u00 + u01;  pq[mt*2]   += u00*u00 + u01*u01;
                ps[mt*2+1] += u10 + u11;  pq[mt*2+1] += u10*u10 + u11*u11;
            }
        }
        #pragma unroll
        for (int o = 1; o < 4; o <<= 1) {
            #pragma unroll
            for (int p = 0; p < 8; p++) {
                ps[p] += __shfl_xor_sync(0xffffffffu, ps[p], o);
                pq[p] += __shfl_xor_sync(0xffffffffu, pq[p], o);
            }
        }
        int wnIdx = warp & 3;
        if ((lane & 3) == 0) {
            #pragma unroll
            for (int mt = 0; mt < 4; mt++) {
                int lr = wm + mt * 16 + (lane >> 2);
                ssum[wnIdx * 128 + lr]     = ps[mt*2];
                ssq [wnIdx * 128 + lr]     = pq[mt*2];
                ssum[wnIdx * 128 + lr + 8] = ps[mt*2+1];
                ssq [wnIdx * 128 + lr + 8] = pq[mt*2+1];
            }
        }
        __syncthreads();
        float* Cf = (float*)C;
        #pragma unroll
        for (int mt = 0; mt < 4; mt++) {
            int lr0 = wm + mt * 16 + (lane >> 2);
            int lr1 = lr0 + 8;
            float s0 = ssum[lr0] + ssum[128+lr0] + ssum[256+lr0] + ssum[384+lr0];
            float q0 = ssq[lr0]  + ssq[128+lr0]  + ssq[256+lr0]  + ssq[384+lr0];
            float s1 = ssum[lr1] + ssum[128+lr1] + ssum[256+lr1] + ssum[384+lr1];
            float q1 = ssq[lr1]  + ssq[128+lr1]  + ssq[256+lr1]  + ssq[384+lr1];
            float mu0 = s0 * (1.f/128.f);
            float iv0 = rsqrtf(q0 * (1.f/128.f) - mu0*mu0 + 1e-5f);
            float mu1 = s1 * (1.f/128.f);
            float iv1 = rsqrtf(q1 * (1.f/128.f) - mu1*mu1 + 1e-5f);
            #pragma unroll
            for (int nt = 0; nt < 4; nt++) {
                int gc = wn + nt * 8 + 2 * (lane & 3);
                float g0 = gammap[gc], g1 = gammap[gc+1];
                float b0 = betap[gc],  b1 = betap[gc+1];
                Cf[xr[mt*2]   + gc]     = (c[mt][nt][0] - mu0) * iv0 * g0 + b0;
                Cf[xr[mt*2]   + gc + 1] = (c[mt][nt][1] - mu0) * iv0 * g1 + b1;
                Cf[xr[mt*2+1] + gc]     = (c[mt][nt][2] - mu1) * iv1 * g0 + b0;
                Cf[xr[mt*2+1] + gc + 1] = (c[mt][nt][3] - mu1) * iv1 * g1 + b1;
            }
        }
        return;
    }

    #pragma unroll
    for (int mt = 0; mt < 4; mt++) {
        #pragma unroll
        for (int nt = 0; nt < 4; nt++) {
            int gr = blockM + wm + mt * 16 + (lane >> 2);
            int gc = blockN + wn + nt * 8 + 2 * (lane & 3);
            float bv0 = bias[gc], bv1 = bias[gc + 1];
            float v00 = c[mt][nt][0] + bv0, v01 = c[mt][nt][1] + bv1;
            float v10 = c[mt][nt][2] + bv0, v11 = c[mt][nt][3] + bv1;
            int gr1 = gr + 8;
            __half2 h0 = __floats2half2_rn(v00, v01);
            __half2 h1 = __floats2half2_rn(v10, v11);
            if (MODE == 0) {
                __half* Ch = (__half*)C;
                *(__half2*)(Ch + (size_t)gr * N + gc)  = h0;
                *(__half2*)(Ch + (size_t)gr1 * N + gc) = h1;
            } else if (MODE == 7) {
                float* Cf = (float*)C;
                size_t or0 = (size_t)((gr  >> 9) * 12 + pos) * 512 + (gr  & 511);
                size_t or1 = (size_t)((gr1 >> 9) * 12 + pos) * 512 + (gr1 & 511);
                float* p0 = Cf + or0 * 256 + gc;
                float* p1 = Cf + or1 * 256 + gc;
                p0[0] = v00; p0[1] = v01; p1[0] = v10; p1[1] = v11;
            } else if (MODE == 3) {
                __half* Ch = (__half*)C;
                *(__half2*)(Ch + (size_t)gr * N + gc)  = h0;
                *(__half2*)(Ch + (size_t)gr1 * N + gc) = h1;
                if (gc >= 128 && gc < 256) {
                    *(__half2*)(Kc + (size_t)gr * 128 + gc - 128)  = h0;
                    *(__half2*)(Kc + (size_t)gr1 * 128 + gc - 128) = h1;
                } else if (gc >= 256) {
                    *(__half2*)(Vc + (size_t)gr * 128 + gc - 256)  = h0;
                    *(__half2*)(Vc + (size_t)gr1 * 128 + gc - 256) = h1;
                }
            } else { // MODE 4
                __half* Ch = (__half*)C;
                if (gc < 128) {
                    *(__half2*)(Ch + (size_t)gr * 128 + gc)  = h0;
                    *(__half2*)(Ch + (size_t)gr1 * 128 + gc) = h1;
                } else if (gc < 256) {
                    *(__half2*)(Kc + ((size_t)pos * BN_ + gr) * 128 + gc - 128)  = h0;
                    *(__half2*)(Kc + ((size_t)pos * BN_ + gr1) * 128 + gc - 128) = h1;
                } else {
                    *(__half2*)(Vc + ((size_t)pos * BN_ + gr) * 128 + gc - 256)  = h0;
                    *(__half2*)(Vc + ((size_t)pos * BN_ + gr1) * 128 + gc - 256) = h1;
                }
            }
        }
    }
}

// ---------------- prep kernels ----------------
__global__ void pe_init_kernel(float* pe) {
    int idx = blockIdx.x * blockDim.x + threadIdx.x;
    if (idx >= 64 * 128) return;
    int pos = idx >> 7, d = idx & 127;
    int j = d >> 1;
    float div = expf((float)(2 * j) * (-logf(10000.f) / 128.f));
    float ang = (float)pos * div;
    pe[idx] = (d & 1) ? cosf(ang) : sinf(ang);
}

__global__ void halfw_a_kernel(const float* __restrict__ w_ih, const float* __restrict__ w_hh,
                               const float* __restrict__ in_w,
                               __half* wih, __half* whh, __half* inw) {
    int i = blockIdx.x * blockDim.x + threadIdx.x;
    if (i < 49152)       wih[i]         = __float2half(w_ih[i]);
    else if (i < 98304)  whh[i - 49152] = __float2half(w_hh[i - 49152]);
    else if (i < 147456) inw[i - 98304] = __float2half(in_w[i - 98304]);
}

__global__ void xconv_kernel(const float* __restrict__ X, __half* __restrict__ Xs) {
    int idx = blockIdx.x * blockDim.x + threadIdx.x;
    if (idx >= LBN_ * 32) return;
    int d4 = (idx & 31) * 4;
    int row = idx >> 5;
    int l = row >> 14, rem = row & 16383, b = rem >> 9, n = rem & 511;
    float4 v = *(const float4*)(X + (((size_t)(b * 12 + l) * 512 + n) << 7) + d4);
    *(__half2*)(Xs + (size_t)row * 128 + d4)     = __floats2half2_rn(v.x, v.y);
    *(__half2*)(Xs + (size_t)row * 128 + d4 + 2) = __floats2half2_rn(v.z, v.w);
}

__global__ void prefuse_kernel(const float* __restrict__ W1, const float* __restrict__ W2,
                               const float* __restrict__ b2, const float* __restrict__ b1,
                               __half* __restrict__ Wout, float* __restrict__ bout, int R) {
    int idx = blockIdx.x * blockDim.x + threadIdx.x;
    if (idx >= R * 128) return;
    int r = idx >> 7, k = idx & 127;
    float acc = 0.f;
    #pragma unroll 4
    for (int j = 0; j < 128; j++) acc += W1[r * 128 + j] * W2[j * 128 + k];
    Wout[idx] = __float2half(acc);
    if (k == 0) {
        float b = 0.f;
        for (int j = 0; j < 128; j++) b += W1[r * 128 + j] * b2[j];
        bout[r] = b + (b1 ? b1[r] : 0.f);
    }
}

__global__ void kvpe_kernel(const float* __restrict__ attn_in_w, const float* __restrict__ pe,
                            float* __restrict__ Kpe, float* __restrict__ Vpe) {
    int idx = blockIdx.x * blockDim.x + threadIdx.x;
    if (idx >= 24 * 256) return;
    int pos = idx >> 8, c = idx & 255;
    const float* wrow = attn_in_w + (size_t)(128 + c) * 128;
    const float* prow = pe + pos * 128;
    float acc = 0.f;
    #pragma unroll 4
    for (int d = 0; d < 128; d++) acc += wrow[d] * prow[d];
    if (c < 128) Kpe[pos * 128 + c] = acc;
    else         Vpe[pos * 128 + (c - 128)] = acc;
}

// ---------------- GRU gates (fp16 I/O, half2-vectorized) ----------------
__global__ void gru_gates_kernel(const __half* __restrict__ gi, const __half* __restrict__ gh,
                                 const __half* __restrict__ h, __half* __restrict__ hnew,
                                 __half* __restrict__ hnext, const float* __restrict__ pe_row,
                                 const float* __restrict__ bhh, int total2) {
    int idx = blockIdx.x * blockDim.x + threadIdx.x;
    if (idx >= total2) return;
    int row = idx >> 6, d2 = (idx & 63) * 2;
    size_t b3 = (size_t)row * 384;
    float2 ir  = __half22float2(*(const __half2*)(gi + b3 + d2));
    float2 iz  = __half22float2(*(const __half2*)(gi + b3 + 128 + d2));
    float2 in_ = __half22float2(*(const __half2*)(gi + b3 + 256 + d2));
    float2 hr, hz, hn;
    if (gh) {
        hr = __half22float2(*(const __half2*)(gh + b3 + d2));
        hz = __half22float2(*(const __half2*)(gh + b3 + 128 + d2));
        hn = __half22float2(*(const __half2*)(gh + b3 + 256 + d2));
    } else {
        hr = make_float2(bhh[d2], bhh[d2 + 1]);
        hz = make_float2(bhh[128 + d2], bhh[128 + d2 + 1]);
        hn = make_float2(bhh[256 + d2], bhh[256 + d2 + 1]);
    }
    float2 hv = h ? __half22float2(*(const __half2*)(h + (size_t)row * 128 + d2))
                  : make_float2(0.f, 0.f);
    float r0 = sigmoid_f(ir.x + hr.x), r1 = sigmoid_f(ir.y + hr.y);
    float z0 = sigmoid_f(iz.x + hz.x), z1 = sigmoid_f(iz.y + hz.y);
    float n0 = tanh_f(in_.x + r0 * hn.x), n1 = tanh_f(in_.y + r1 * hn.y);
    float o0 = (1.f - z0) * n0 + z0 * hv.x;
    float o1 = (1.f - z1) * n1 + z1 * hv.y;
    *(__half2*)(hnew + (size_t)row * 128 + d2) = __floats2half2_rn(o0, o1);
    if (hnext)
        *(__half2*)(hnext + (size_t)row * 128 + d2) =
            __floats2half2_rn(o0 + pe_row[d2], o1 + pe_row[d2 + 1]);
}

// ---------------- encoder self-attention ----------------
__global__ void enc_attn_kernel(const __half* __restrict__ QKV, __half* __restrict__ O,
                                __half* __restrict__ ares0) {
    int bn = blockIdx.x;
    int w = threadIdx.x >> 5, lane = threadIdx.x & 31;
    __shared__ float q[4][12][32];
    __shared__ float k[4][12][33];
    __shared__ float v[4][12][33];
    __shared__ float s[4][12][13];

    for (int e = lane; e < 12 * 16; e += 32) {
        int l = e >> 4, d2 = (e & 15) * 2;
        size_t base = ((size_t)l * BN_ + bn) * 384 + w * 32 + d2;
        float2 qv = __half22float2(*(const __half2*)(QKV + base));
        float2 kv = __half22float2(*(const __half2*)(QKV + base + 128));
        float2 vv = __half22float2(*(const __half2*)(QKV + base + 256));
        q[w][l][d2] = qv.x; q[w][l][d2+1] = qv.y;
        k[w][l][d2] = kv.x; k[w][l][d2+1] = kv.y;
        v[w][l][d2] = vv.x; v[w][l][d2+1] = vv.y;
    }
    __syncwarp();
    const float scale = 0.17677669529663687f;
    if (lane < 12) {
        int j = lane;
        #pragma unroll
        for (int i = 0; i < 12; i++) {
            float acc = 0.f;
            #pragma unroll
            for (int d = 0; d < 32; d++) acc += q[w][i][d] * k[w][j][d];
            s[w][i][j] = acc * scale;
        }
    }
    __syncwarp();
    if (lane < 12) {
        int i = lane;
        float mx = -1e30f;
        #pragma unroll
        for (int j = 0; j < 12; j++) mx = fmaxf(mx, s[w][i][j]);
        float sum = 0.f;
        #pragma unroll
        for (int j = 0; j < 12; j++) { float e = __expf(s[w][i][j] - mx); s[w][i][j] = e; sum += e; }
        float inv = __fdividef(1.f, sum);
        #pragma unroll
        for (int j = 0; j < 12; j++) s[w][i][j] *= inv;
    }
    __syncwarp();
    {
        int d = lane;
        #pragma unroll
        for (int i = 0; i < 12; i++) {
            float acc = 0.f;
            #pragma unroll
            for (int j = 0; j < 12; j++) acc += s[w][i][j] * v[w][j][d];
            __half hv = __float2half(acc);
            O[((size_t)i * BN_ + bn) * 128 + w * 32 + d] = hv;
            if (i == 11) ares0[(size_t)bn * 128 + w * 32 + d] = hv;
        }
    }
}

// ---------------- decode attention (fp16 KV/Q, PE-drift multipliers) ----------------
__global__ void dec_attn_kernel(const __half* __restrict__ Qbuf,
                                const __half* __restrict__ Kc, const __half* __restrict__ Vc,
                                const float* __restrict__ Kpe, const float* __restrict__ Vpe,
                                __half* __restrict__ O, int t) {
    int len = 12 + t;
    int bn = blockIdx.x;
    int w = threadIdx.x >> 5, lane = threadIdx.x & 31;
    __shared__ float qs[4][32];
    __shared__ float Kb[4][23][33];
    __shared__ float Vb[4][23][33];
    __shared__ float aw[4][23];

    qs[w][lane] = __half2float(Qbuf[(size_t)bn * 128 + w * 32 + lane]);
    for (int e = lane; e < len * 16; e += 32) {
        int i = e >> 4, d2 = (e & 15) * 2;
        size_t src = ((size_t)i * BN_ + bn) * 128 + w * 32 + d2;
        float2 kv = __half22float2(*(const __half2*)(Kc + src));
        float2 vv = __half22float2(*(const __half2*)(Vc + src));
        Kb[w][i][d2] = kv.x; Kb[w][i][d2+1] = kv.y;
        Vb[w][i][d2] = vv.x; Vb[w][i][d2+1] = vv.y;
    }
    __syncwarp();

    float sc = -1e30f;
    int i = lane;
    if (i < len) {
        float m = (i < 12) ? (float)(t - 1) : (float)(t - i + 12);
        float a = 0.f, ap = 0.f;
        #pragma unroll
        for (int d = 0; d < 32; d++) {
            float qd = qs[w][d];
            a  += Kb[w][i][d] * qd;
            ap += Kpe[i * 128 + w * 32 + d] * qd;
        }
        sc = (a + m * ap) * 0.17677669529663687f;
    }
    float mx = sc;
    #pragma unroll
    for (int o = 16; o > 0; o >>= 1) mx = fmaxf(mx, __shfl_xor_sync(0xffffffffu, mx, o));
    float e = (i < len) ? __expf(sc - mx) : 0.f;
    float sum = e;
    #pragma unroll
    for (int o = 16; o > 0; o >>= 1) sum += __shfl_xor_sync(0xffffffffu, sum, o);
    float a = __fdividef(e, sum);
    if (i < len) aw[w][i] = a;
    __syncwarp();

    int d = lane;
    float acc = 0.f;
    for (int j = 0; j < len; j++) {
        float mj = (j < 12) ? (float)(t - 1) : (float)(t - j + 12);
        acc += aw[w][j] * (Vb[w][j][d] + mj * Vpe[j * 128 + w * 32 + d]);
    }
    O[(size_t)bn * 128 + w * 32 + d] = __float2half(acc);
}

// ---------------- host ----------------
static inline float* symaddr(const void* sym) {
    void* p = nullptr;
    cudaGetSymbolAddress(&p, sym);
    return (float*)p;
}
static inline __half* symaddr_h(const void* sym) {
    void* p = nullptr;
    cudaGetSymbolAddress(&p, sym);
    return (__half*)p;
}

template <int MODE>
static inline void launch_gemm(cudaStream_t st,
                               const __half* A, const __half* W, const float* b, void* C,
                               int M, int N, int pos = 0,
                               __half* Kc = nullptr, __half* Vc = nullptr,
                               const float* Xg = nullptr,
                               const float* gam = nullptr, const float* bet = nullptr) {
    gemm3<MODE><<<dim3(N / 128, M / 128, 1), 256, GSMEM_BYTES, st>>>(
        A, W, b, C, M, N, pos, Kc, Vc, Xg, gam, bet);
}

extern "C" void kernel_launch(void* const* d_in, const int* in_sizes, int n_in,
                              void* d_out, int out_size) {
    const float* X          = (const float*)d_in[0];
    const float* gru_w_ih   = (const float*)d_in[1];
    const float* gru_w_hh   = (const float*)d_in[2];
    const float* gru_b_ih   = (const float*)d_in[3];
    const float* gru_b_hh   = (const float*)d_in[4];
    const float* attn_in_w  = (const float*)d_in[5];
    const float* attn_in_b  = (const float*)d_in[6];
    const float* attn_out_w = (const float*)d_in[7];
    const float* attn_out_b = (const float*)d_in[8];
    const float* backcast_w = (const float*)d_in[9];
    const float* backcast_b = (const float*)d_in[10];
    const float* forecast_w = (const float*)d_in[11];
    const float* forecast_b = (const float*)d_in[12];
    const float* ln_gamma   = (const float*)d_in[13];
    const float* ln_beta    = (const float*)d_in[14];

    float* out  = (float*)d_out;
    float* res  = out;
    float* fore = out + RES_ELEMS;

    __half* Xs     = symaddr_h(g_Xs);
    __half* GI     = symaddr_h(g_GI);
    __half* GH     = symaddr_h(g_GH);
    __half* rnn    = symaddr_h(g_rnn);
    __half* rnnpe  = symaddr_h(g_rnnpe);
    __half* QKV    = symaddr_h(g_QKV);
    __half* attn   = symaddr_h(g_attn);
    __half* Kc     = symaddr_h(g_Kc);
    __half* Vc     = symaddr_h(g_Vc);
    __half* aresU  = symaddr_h(g_aresU);
    __half* Qbuf   = symaddr_h(g_Qbuf);
    __half* GIdec  = symaddr_h(g_GIdec);
    __half* GHdec  = symaddr_h(g_GHdec);
    __half* gbuf   = symaddr_h(g_g);
    __half* hlast  = symaddr_h(g_hlast);
    float*  pe     = symaddr(g_pe);
    float*  Kpe    = symaddr(g_Kpe);
    float*  Vpe    = symaddr(g_Vpe);
    __half* wih_h  = symaddr_h(g_wih_h);
    __half* whh_h  = symaddr_h(g_whh_h);
    __half* inw_h  = symaddr_h(g_inw_h);
    __half* Wf     = symaddr_h(g_Wf);
    float*  bf     = symaddr(g_bf);
    __half* Wbo    = symaddr_h(g_Wbo);
    float*  bbo    = symaddr(g_bbo);
    __half* Wfo    = symaddr_h(g_Wfo);
    float*  ffo    = symaddr(g_ffo);

    static bool inited = false;
    static cudaStream_t s2 = 0, s3 = 0;
    static cudaEvent_t evF = 0, evB1 = 0, evEnc = 0, evM1 = 0, evW = 0, evS3 = 0;
    static cudaEvent_t evGH[13], evGate[13], evA[12];
    if (!inited) {
        cudaFuncSetAttribute(gemm3<0>, cudaFuncAttributeMaxDynamicSharedMemorySize, GSMEM_BYTES);
        cudaFuncSetAttribute(gemm3<3>, cudaFuncAttributeMaxDynamicSharedMemorySize, GSMEM_BYTES);
        cudaFuncSetAttribute(gemm3<4>, cudaFuncAttributeMaxDynamicSharedMemorySize, GSMEM_BYTES);
        cudaFuncSetAttribute(gemm3<6>, cudaFuncAttributeMaxDynamicSharedMemorySize, GSMEM_BYTES);
        cudaFuncSetAttribute(gemm3<7>, cudaFuncAttributeMaxDynamicSharedMemorySize, GSMEM_BYTES);
        cudaStreamCreateWithFlags(&s2, cudaStreamNonBlocking);
        cudaStreamCreateWithFlags(&s3, cudaStreamNonBlocking);
        cudaEventCreateWithFlags(&evF,   cudaEventDisableTiming);
        cudaEventCreateWithFlags(&evB1,  cudaEventDisableTiming);
        cudaEventCreateWithFlags(&evEnc, cudaEventDisableTiming);
        cudaEventCreateWithFlags(&evM1,  cudaEventDisableTiming);
        cudaEventCreateWithFlags(&evW,   cudaEventDisableTiming);
        cudaEventCreateWithFlags(&evS3,  cudaEventDisableTiming);
        for (int i = 0; i < 13; i++) {
            cudaEventCreateWithFlags(&evGH[i],   cudaEventDisableTiming);
            cudaEventCreateWithFlags(&evGate[i], cudaEventDisableTiming);
        }
        for (int i = 0; i < 12; i++)
            cudaEventCreateWithFlags(&evA[i], cudaEventDisableTiming);
        inited = true;
    }

    const int TPB = 256;
    const cudaStream_t s0 = 0;

    // ---- s0 prep (evF recorded first so side streams can fork legally) ----
    pe_init_kernel<<<(64 * 128 + TPB - 1) / TPB, TPB, 0, s0>>>(pe);
    cudaEventRecord(evF, s0);
    halfw_a_kernel<<<(147456 + TPB - 1) / TPB, TPB, 0, s0>>>(gru_w_ih, gru_w_hh, attn_in_w,
                                                             wih_h, whh_h, inw_h);
    xconv_kernel<<<LBN_ * 32 / TPB, TPB, 0, s0>>>(X, Xs);

    // ---- s3: fork off evF, weight prefusions ----
    cudaStreamWaitEvent(s3, evF, 0);
    prefuse_kernel<<<(49152 + TPB - 1) / TPB, TPB, 0, s3>>>(gru_w_ih, attn_out_w, attn_out_b,
                                                            gru_b_ih, Wf, bf, 384);
    prefuse_kernel<<<(16384 + TPB - 1) / TPB, TPB, 0, s3>>>(backcast_w, attn_out_w, attn_out_b,
                                                            backcast_b, Wbo, bbo, 128);
    prefuse_kernel<<<(32768 + TPB - 1) / TPB, TPB, 0, s3>>>(forecast_w, attn_out_w, attn_out_b,
                                                            forecast_b, Wfo, ffo, 256);
    cudaEventRecord(evW, s3);

    // ---- s2: fork off evF, kvpe ----
    cudaStreamWaitEvent(s2, evF, 0);
    kvpe_kernel<<<(24 * 256 + TPB - 1) / TPB, TPB, 0, s2>>>(attn_in_w, pe, Kpe, Vpe);
    cudaEventRecord(evB1, s2);

    // ---- GI for all encoder steps ----
    launch_gemm<0>(s0, Xs, wih_h, gru_b_ih, GI, LBN_, 384);

    // ---- GRU encode ----
    gru_gates_kernel<<<BN_ * 64 / TPB, TPB, 0, s0>>>(GI, nullptr, nullptr,
                                                     rnn, rnnpe, pe, gru_b_hh, BN_ * 64);
    for (int l = 1; l < 12; l++) {
        launch_gemm<0>(s0, rnn + (size_t)(l - 1) * BN_ * 128, whh_h, gru_b_hh, GH, BN_, 384);
        gru_gates_kernel<<<BN_ * 64 / TPB, TPB, 0, s0>>>(GI + (size_t)l * BN_ * 384, GH,
                                                         rnn + (size_t)(l - 1) * BN_ * 128,
                                                         rnn + (size_t)l * BN_ * 128,
                                                         rnnpe + (size_t)l * BN_ * 128,
                                                         pe + l * 128, nullptr, BN_ * 64);
    }
    cudaEventRecord(evEnc, s0);

    // ---- s2: GH_1 (needs rnn[11] only) ----
    cudaStreamWaitEvent(s2, evEnc, 0);
    launch_gemm<0>(s2, rnn + (size_t)11 * BN_ * 128, whh_h, gru_b_hh, GHdec, BN_, 384);
    cudaEventRecord(evGH[1], s2);

    // ---- encoder MHA ----
    launch_gemm<3>(s0, rnnpe, inw_h, attn_in_b, QKV, LBN_, 384, 0, Kc, Vc);
    enc_attn_kernel<<<BN_, 128, 0, s0>>>(QKV, attn, aresU);
    cudaEventRecord(evM1, s0);
    cudaEventRecord(evA[0], s0);

    // ---- s3: backcast + LN, then forecast slices as they become ready ----
    cudaStreamWaitEvent(s3, evM1, 0);
    launch_gemm<6>(s3, attn, Wbo, bbo, res, LBN_, 128, 0, nullptr, nullptr,
                   X, ln_gamma, ln_beta);
    cudaStreamWaitEvent(s3, evA[0], 0);
    launch_gemm<7>(s3, aresU, Wfo, ffo, fore, BN_, 256, 0);

    // ---- GI_1 (prefused Wf, A = aresU[0] = attn last) ----
    cudaStreamWaitEvent(s0, evW, 0);
    launch_gemm<0>(s0, aresU, Wf, bf, GIdec, BN_, 384);

    // ---- decode loop: gates -> proj -> attn -> GI_{t+1} on s0; GH on s2; fore slices on s3 ----
    cudaStreamWaitEvent(s0, evB1, 0);
    const __half* hl = rnn + (size_t)11 * BN_ * 128;
    for (int t = 1; t <= 11; t++) {
        cudaStreamWaitEvent(s0, evGH[t], 0);
        gru_gates_kernel<<<BN_ * 64 / TPB, TPB, 0, s0>>>(GIdec, GHdec, hl, gbuf,
                                                         hlast, pe + (11 + t) * 128,
                                                         nullptr, BN_ * 64);
        hl = hlast;
        if (t < 11) {
            cudaEventRecord(evGate[t], s0);
            cudaStreamWaitEvent(s2, evGate[t], 0);
            launch_gemm<0>(s2, hlast, whh_h, gru_b_hh, GHdec, BN_, 384);
            cudaEventRecord(evGH[t + 1], s2);
        }
        launch_gemm<4>(s0, gbuf, inw_h, attn_in_b, Qbuf, BN_, 384, 11 + t, Kc, Vc);
        dec_attn_kernel<<<BN_, 128, 0, s0>>>(Qbuf, Kc, Vc, Kpe, Vpe,
                                             aresU + (size_t)t * BN_ * 128, t);
        if (t < 11) {
            cudaEventRecord(evA[t], s0);
            cudaStreamWaitEvent(s3, evA[t], 0);
            launch_gemm<7>(s3, aresU + (size_t)t * BN_ * 128, Wfo, ffo, fore, BN_, 256, t);
            launch_gemm<0>(s0, aresU + (size_t)t * BN_ * 128, Wf, bf, GIdec, BN_, 384);
        }
    }
    cudaEventRecord(evS3, s3);

    // ---- tail: last forecast slice launches immediately on s0 (only needs aresU[11]);
    //      the s3 join happens after it, off the critical path ----
    launch_gemm<7>(s0, aresU + (size_t)11 * BN_ * 128, Wfo, ffo, fore, BN_, 256, 11);
    cudaStreamWaitEvent(s0, evS3, 0);
}